// round 1
// baseline (speedup 1.0000x reference)
#include <cuda_runtime.h>
#include <math.h>

// Problem constants
#define NN 8192
#define DD 512
#define BR 64      // query rows per CTA
#define BC 64      // kv cols per tile
#define KCH 64     // k-dim staging chunk for S gemm
#define DCH 64     // d-dim chunk for PV gemm

// Scratch for Q, K, V projections (allocation-free rule: __device__ globals)
__device__ float g_q[NN * DD];
__device__ float g_k[NN * DD];
__device__ float g_v[NN * DD];

// ---------------------------------------------------------------------------
// Kernel 1: y = x @ W^T + b   for W in {Wq, Wk, Wv}, selected by blockIdx.z.
// Classic 128x128x8 register-tiled SGEMM. x[N,D], W[D,D] row-major, both
// k-contiguous (NT gemm).
// ---------------------------------------------------------------------------
__global__ __launch_bounds__(256, 2)
void qkv_proj_kernel(const float* __restrict__ x,
                     const float* __restrict__ Wq, const float* __restrict__ bq,
                     const float* __restrict__ Wk, const float* __restrict__ bk,
                     const float* __restrict__ Wv, const float* __restrict__ bv) {
    __shared__ float As[8 * 128];
    __shared__ float Bs[8 * 128];

    const float* W;
    const float* bias;
    float* out;
    if (blockIdx.z == 0)      { W = Wq; bias = bq; out = g_q; }
    else if (blockIdx.z == 1) { W = Wk; bias = bk; out = g_k; }
    else                      { W = Wv; bias = bv; out = g_v; }

    const int t  = threadIdx.x;
    const int m0 = blockIdx.y * 128;
    const int n0 = blockIdx.x * 128;

    const int tm = (t >> 4) * 8;   // 0..120 step 8
    const int tn = (t & 15) * 8;

    float acc[8][8];
#pragma unroll
    for (int i = 0; i < 8; ++i)
#pragma unroll
        for (int j = 0; j < 8; ++j) acc[i][j] = 0.0f;

    const int mload = t >> 1;        // 0..127
    const int k4    = (t & 1) * 4;   // 0 or 4

    const float4* As4 = (const float4*)As;
    const float4* Bs4 = (const float4*)Bs;

    for (int k0 = 0; k0 < DD; k0 += 8) {
        float4 av = *(const float4*)&x[(size_t)(m0 + mload) * DD + k0 + k4];
        float4 bv4 = *(const float4*)&W[(size_t)(n0 + mload) * DD + k0 + k4];
        __syncthreads();
        As[(k4 + 0) * 128 + mload] = av.x;
        As[(k4 + 1) * 128 + mload] = av.y;
        As[(k4 + 2) * 128 + mload] = av.z;
        As[(k4 + 3) * 128 + mload] = av.w;
        Bs[(k4 + 0) * 128 + mload] = bv4.x;
        Bs[(k4 + 1) * 128 + mload] = bv4.y;
        Bs[(k4 + 2) * 128 + mload] = bv4.z;
        Bs[(k4 + 3) * 128 + mload] = bv4.w;
        __syncthreads();
#pragma unroll
        for (int kk = 0; kk < 8; ++kk) {
            float4 a0 = As4[kk * 32 + (t >> 4) * 2];
            float4 a1 = As4[kk * 32 + (t >> 4) * 2 + 1];
            float4 b0 = Bs4[kk * 32 + (t & 15) * 2];
            float4 b1 = Bs4[kk * 32 + (t & 15) * 2 + 1];
            float a[8] = {a0.x, a0.y, a0.z, a0.w, a1.x, a1.y, a1.z, a1.w};
            float b[8] = {b0.x, b0.y, b0.z, b0.w, b1.x, b1.y, b1.z, b1.w};
#pragma unroll
            for (int i = 0; i < 8; ++i)
#pragma unroll
                for (int j = 0; j < 8; ++j)
                    acc[i][j] = fmaf(a[i], b[j], acc[i][j]);
        }
    }

    // epilogue: add bias, write out
#pragma unroll
    for (int i = 0; i < 8; ++i) {
        float* orow = &out[(size_t)(m0 + tm + i) * DD + n0 + tn];
        float4 o0 = make_float4(acc[i][0] + bias[n0 + tn + 0],
                                acc[i][1] + bias[n0 + tn + 1],
                                acc[i][2] + bias[n0 + tn + 2],
                                acc[i][3] + bias[n0 + tn + 3]);
        float4 o1 = make_float4(acc[i][4] + bias[n0 + tn + 4],
                                acc[i][5] + bias[n0 + tn + 5],
                                acc[i][6] + bias[n0 + tn + 6],
                                acc[i][7] + bias[n0 + tn + 7]);
        *(float4*)&orow[0] = o0;
        *(float4*)&orow[4] = o1;
    }
}

// ---------------------------------------------------------------------------
// Kernel 2: flash attention with encoding biases.
// One CTA per 64 query rows. O[64][512] lives in SMEM. K/V streamed in
// 64-wide tiles (K,V are L2-resident: 32 MB total vs 126 MB L2).
// ---------------------------------------------------------------------------
#define SMEM_FLOATS (32768 /*Os*/ + 4096 /*Ss*/ + 8192 /*Ust*/ + 192 /*m,l,f*/)
#define SMEM_BYTES  (SMEM_FLOATS * 4)

__global__ __launch_bounds__(256, 1)
void flash_attn_kernel(const float* __restrict__ spatial,
                       const float* __restrict__ edge,
                       float* __restrict__ outp) {
    extern __shared__ float sm[];
    float* Os   = sm;                    // [64][512]
    float* Ss   = sm + 32768;            // [64][64]
    float* Ust  = sm + 32768 + 4096;     // staging: Qc(4096) + Kc(4096) | Vc(4096)
    float* mrow = Ust + 8192;            // [64]
    float* lrow = mrow + 64;             // [64]
    float* frow = lrow + 64;             // [64]

    float4* Os4       = (float4*)Os;
    const float4* Qc4 = (const float4*)Ust;
    const float4* Kc4 = (const float4*)(Ust + 4096);
    const float4* Vc4 = (const float4*)Ust;

    const int t   = threadIdx.x;
    const int tm4 = t >> 4;        // 0..15
    const int tm  = tm4 * 4;
    const int tn4 = t & 15;        // 0..15
    const int m0  = blockIdx.x * BR;

    const float scale = 0.044194173824159216f;  // 1/sqrt(512)

    // init O, m, l
    for (int idx = t; idx < 8192; idx += 256)
        Os4[idx] = make_float4(0.f, 0.f, 0.f, 0.f);
    if (t < 64) { mrow[t] = -INFINITY; lrow[t] = 0.0f; }
    __syncthreads();

    for (int j = 0; j < NN / BC; ++j) {
        const int n0 = j * BC;

        // ---- S = Q Kt (64x64), k-chunked through SMEM ----
        float sacc[4][4];
#pragma unroll
        for (int i = 0; i < 4; ++i)
#pragma unroll
            for (int jj = 0; jj < 4; ++jj) sacc[i][jj] = 0.0f;

        for (int kc = 0; kc < DD; kc += KCH) {
            __syncthreads();
#pragma unroll
            for (int i = 0; i < 4; ++i) {
                int f4 = t + i * 256;
                int mm = f4 & 63;
                int c4 = f4 >> 6;   // 0..15
                float4 qv = *(const float4*)&g_q[(size_t)(m0 + mm) * DD + kc + c4 * 4];
                float4 kv = *(const float4*)&g_k[(size_t)(n0 + mm) * DD + kc + c4 * 4];
                Ust[(c4 * 4 + 0) * 64 + mm] = qv.x;
                Ust[(c4 * 4 + 1) * 64 + mm] = qv.y;
                Ust[(c4 * 4 + 2) * 64 + mm] = qv.z;
                Ust[(c4 * 4 + 3) * 64 + mm] = qv.w;
                Ust[4096 + (c4 * 4 + 0) * 64 + mm] = kv.x;
                Ust[4096 + (c4 * 4 + 1) * 64 + mm] = kv.y;
                Ust[4096 + (c4 * 4 + 2) * 64 + mm] = kv.z;
                Ust[4096 + (c4 * 4 + 3) * 64 + mm] = kv.w;
            }
            __syncthreads();
#pragma unroll 8
            for (int kk = 0; kk < KCH; ++kk) {
                float4 a = Qc4[kk * 16 + tm4];
                float4 b = Kc4[kk * 16 + tn4];
                sacc[0][0] = fmaf(a.x, b.x, sacc[0][0]);
                sacc[0][1] = fmaf(a.x, b.y, sacc[0][1]);
                sacc[0][2] = fmaf(a.x, b.z, sacc[0][2]);
                sacc[0][3] = fmaf(a.x, b.w, sacc[0][3]);
                sacc[1][0] = fmaf(a.y, b.x, sacc[1][0]);
                sacc[1][1] = fmaf(a.y, b.y, sacc[1][1]);
                sacc[1][2] = fmaf(a.y, b.z, sacc[1][2]);
                sacc[1][3] = fmaf(a.y, b.w, sacc[1][3]);
                sacc[2][0] = fmaf(a.z, b.x, sacc[2][0]);
                sacc[2][1] = fmaf(a.z, b.y, sacc[2][1]);
                sacc[2][2] = fmaf(a.z, b.z, sacc[2][2]);
                sacc[2][3] = fmaf(a.z, b.w, sacc[2][3]);
                sacc[3][0] = fmaf(a.w, b.x, sacc[3][0]);
                sacc[3][1] = fmaf(a.w, b.y, sacc[3][1]);
                sacc[3][2] = fmaf(a.w, b.z, sacc[3][2]);
                sacc[3][3] = fmaf(a.w, b.w, sacc[3][3]);
            }
        }
        // store scaled scores to Ss
#pragma unroll
        for (int i = 0; i < 4; ++i) {
            ((float4*)Ss)[(tm + i) * 16 + tn4] =
                make_float4(sacc[i][0] * scale, sacc[i][1] * scale,
                            sacc[i][2] * scale, sacc[i][3] * scale);
        }
        __syncthreads();

        // ---- softmax over the tile (add encodings, online max/sum) ----
        {
            const int r  = t >> 2;          // 0..63
            const int c0 = (t & 3) * 16;    // 0..48
            const float* sprow = &spatial[(size_t)(m0 + r) * NN + n0 + c0];
            const float* edrow = &edge[(size_t)(m0 + r) * NN + n0 + c0];
            float vals[16];
            float mloc = -INFINITY;
#pragma unroll
            for (int c = 0; c < 16; c += 4) {
                float4 sp = *(const float4*)&sprow[c];
                float4 ed = *(const float4*)&edrow[c];
                float4 ss = *(const float4*)&Ss[r * 64 + c0 + c];
                vals[c + 0] = ss.x + sp.x + ed.x;
                vals[c + 1] = ss.y + sp.y + ed.y;
                vals[c + 2] = ss.z + sp.z + ed.z;
                vals[c + 3] = ss.w + sp.w + ed.w;
                mloc = fmaxf(mloc, fmaxf(fmaxf(vals[c], vals[c + 1]),
                                         fmaxf(vals[c + 2], vals[c + 3])));
            }
            mloc = fmaxf(mloc, __shfl_xor_sync(0xffffffffu, mloc, 1));
            mloc = fmaxf(mloc, __shfl_xor_sync(0xffffffffu, mloc, 2));
            float mold = mrow[r];
            float mnew = fmaxf(mold, mloc);
            float ssum = 0.0f;
#pragma unroll
            for (int c = 0; c < 16; c += 4) {
                float p0 = __expf(vals[c + 0] - mnew);
                float p1 = __expf(vals[c + 1] - mnew);
                float p2 = __expf(vals[c + 2] - mnew);
                float p3 = __expf(vals[c + 3] - mnew);
                *(float4*)&Ss[r * 64 + c0 + c] = make_float4(p0, p1, p2, p3);
                ssum += (p0 + p1) + (p2 + p3);
            }
            ssum += __shfl_xor_sync(0xffffffffu, ssum, 1);
            ssum += __shfl_xor_sync(0xffffffffu, ssum, 2);
            float f = (mold > -1e30f) ? __expf(mold - mnew) : 0.0f;
            if ((t & 3) == 0) {
                mrow[r] = mnew;
                lrow[r] = lrow[r] * f + ssum;
                frow[r] = f;
            }
        }
        __syncthreads();

        // ---- conditional O rescale ----
        for (int idx = t; idx < 8192; idx += 256) {
            float fr = frow[idx >> 7];
            if (fr != 1.0f) {
                float4 o = Os4[idx];
                o.x *= fr; o.y *= fr; o.z *= fr; o.w *= fr;
                Os4[idx] = o;
            }
        }
        __syncthreads();

        // ---- O += P @ V, d-chunked ----
        for (int dch = 0; dch < DD; dch += DCH) {
            __syncthreads();
#pragma unroll
            for (int i = 0; i < 4; ++i) {
                int f4 = t + i * 256;
                int kv = f4 >> 4;    // 0..63
                int c4 = f4 & 15;
                float4 vv = *(const float4*)&g_v[(size_t)(n0 + kv) * DD + dch + c4 * 4];
                ((float4*)Ust)[kv * 16 + c4] = vv;
            }
            __syncthreads();
            float oacc[4][4];
#pragma unroll
            for (int i = 0; i < 4; ++i)
#pragma unroll
                for (int jj = 0; jj < 4; ++jj) oacc[i][jj] = 0.0f;
#pragma unroll 8
            for (int kv = 0; kv < BC; ++kv) {
                float4 b = Vc4[kv * 16 + tn4];
                float a0 = Ss[(tm + 0) * 64 + kv];
                float a1 = Ss[(tm + 1) * 64 + kv];
                float a2 = Ss[(tm + 2) * 64 + kv];
                float a3 = Ss[(tm + 3) * 64 + kv];
                oacc[0][0] = fmaf(a0, b.x, oacc[0][0]);
                oacc[0][1] = fmaf(a0, b.y, oacc[0][1]);
                oacc[0][2] = fmaf(a0, b.z, oacc[0][2]);
                oacc[0][3] = fmaf(a0, b.w, oacc[0][3]);
                oacc[1][0] = fmaf(a1, b.x, oacc[1][0]);
                oacc[1][1] = fmaf(a1, b.y, oacc[1][1]);
                oacc[1][2] = fmaf(a1, b.z, oacc[1][2]);
                oacc[1][3] = fmaf(a1, b.w, oacc[1][3]);
                oacc[2][0] = fmaf(a2, b.x, oacc[2][0]);
                oacc[2][1] = fmaf(a2, b.y, oacc[2][1]);
                oacc[2][2] = fmaf(a2, b.z, oacc[2][2]);
                oacc[2][3] = fmaf(a2, b.w, oacc[2][3]);
                oacc[3][0] = fmaf(a3, b.x, oacc[3][0]);
                oacc[3][1] = fmaf(a3, b.y, oacc[3][1]);
                oacc[3][2] = fmaf(a3, b.z, oacc[3][2]);
                oacc[3][3] = fmaf(a3, b.w, oacc[3][3]);
            }
#pragma unroll
            for (int i = 0; i < 4; ++i) {
                int oi = (tm + i) * 128 + (dch >> 2) + tn4;
                float4 o = Os4[oi];
                o.x += oacc[i][0];
                o.y += oacc[i][1];
                o.z += oacc[i][2];
                o.w += oacc[i][3];
                Os4[oi] = o;
            }
        }
    }

    // ---- finalize: divide by l and write ----
    __syncthreads();
    float4* out4 = (float4*)outp;
    for (int idx = t; idx < 8192; idx += 256) {
        int r2 = idx >> 7;
        float inv = 1.0f / lrow[r2];
        float4 o = Os4[idx];
        o.x *= inv; o.y *= inv; o.z *= inv; o.w *= inv;
        out4[(size_t)(m0 + r2) * 128 + (idx & 127)] = o;
    }
}

// ---------------------------------------------------------------------------
extern "C" void kernel_launch(void* const* d_in, const int* in_sizes, int n_in,
                              void* d_out, int out_size) {
    const float* x       = (const float*)d_in[0];
    const float* spatial = (const float*)d_in[1];
    const float* edge    = (const float*)d_in[2];
    const float* Wq      = (const float*)d_in[3];
    const float* bq      = (const float*)d_in[4];
    const float* Wk      = (const float*)d_in[5];
    const float* bk      = (const float*)d_in[6];
    const float* Wv      = (const float*)d_in[7];
    const float* bv      = (const float*)d_in[8];
    float* out           = (float*)d_out;

    static bool attr_set = false;
    if (!attr_set) {
        cudaFuncSetAttribute(flash_attn_kernel,
                             cudaFuncAttributeMaxDynamicSharedMemorySize,
                             SMEM_BYTES);
        attr_set = true;
    }

    // Kernel 1: Q/K/V projections
    dim3 pgrid(DD / 128, NN / 128, 3);
    qkv_proj_kernel<<<pgrid, 256>>>(x, Wq, bq, Wk, bk, Wv, bv);

    // Kernel 2: flash attention
    flash_attn_kernel<<<NN / BR, 256, SMEM_BYTES>>>(spatial, edge, out);
}

// round 2
// speedup vs baseline: 1.5729x; 1.5729x over previous
#include <cuda_runtime.h>
#include <math.h>

// Problem constants
#define NN 8192
#define DD 512
#define BR 64      // query rows per CTA
#define BC 64      // kv cols per tile
#define KCH 64     // k-dim staging chunk for S gemm
#define DCH 64     // d-dim chunk for PV gemm

// Scratch for Q, K, V projections (allocation-free rule: __device__ globals)
__device__ float g_q[NN * DD];
__device__ float g_k[NN * DD];
__device__ float g_v[NN * DD];

// ---------------------------------------------------------------------------
// Kernel 1: y = x @ W^T + b   for W in {Wq, Wk, Wv}, selected by blockIdx.z.
// Classic 128x128x8 register-tiled SGEMM. x[N,D], W[D,D] row-major, both
// k-contiguous (NT gemm).
// ---------------------------------------------------------------------------
__global__ __launch_bounds__(256, 2)
void qkv_proj_kernel(const float* __restrict__ x,
                     const float* __restrict__ Wq, const float* __restrict__ bq,
                     const float* __restrict__ Wk, const float* __restrict__ bk,
                     const float* __restrict__ Wv, const float* __restrict__ bv) {
    __shared__ float As[8 * 128];
    __shared__ float Bs[8 * 128];

    const float* W;
    const float* bias;
    float* out;
    if (blockIdx.z == 0)      { W = Wq; bias = bq; out = g_q; }
    else if (blockIdx.z == 1) { W = Wk; bias = bk; out = g_k; }
    else                      { W = Wv; bias = bv; out = g_v; }

    const int t  = threadIdx.x;
    const int m0 = blockIdx.y * 128;
    const int n0 = blockIdx.x * 128;

    const int tm = (t >> 4) * 8;   // 0..120 step 8
    const int tn = (t & 15) * 8;

    float acc[8][8];
#pragma unroll
    for (int i = 0; i < 8; ++i)
#pragma unroll
        for (int j = 0; j < 8; ++j) acc[i][j] = 0.0f;

    const int mload = t >> 1;        // 0..127
    const int k4    = (t & 1) * 4;   // 0 or 4

    const float4* As4 = (const float4*)As;
    const float4* Bs4 = (const float4*)Bs;

    for (int k0 = 0; k0 < DD; k0 += 8) {
        float4 av = *(const float4*)&x[(size_t)(m0 + mload) * DD + k0 + k4];
        float4 bv4 = *(const float4*)&W[(size_t)(n0 + mload) * DD + k0 + k4];
        __syncthreads();
        As[(k4 + 0) * 128 + mload] = av.x;
        As[(k4 + 1) * 128 + mload] = av.y;
        As[(k4 + 2) * 128 + mload] = av.z;
        As[(k4 + 3) * 128 + mload] = av.w;
        Bs[(k4 + 0) * 128 + mload] = bv4.x;
        Bs[(k4 + 1) * 128 + mload] = bv4.y;
        Bs[(k4 + 2) * 128 + mload] = bv4.z;
        Bs[(k4 + 3) * 128 + mload] = bv4.w;
        __syncthreads();
#pragma unroll
        for (int kk = 0; kk < 8; ++kk) {
            float4 a0 = As4[kk * 32 + (t >> 4) * 2];
            float4 a1 = As4[kk * 32 + (t >> 4) * 2 + 1];
            float4 b0 = Bs4[kk * 32 + (t & 15) * 2];
            float4 b1 = Bs4[kk * 32 + (t & 15) * 2 + 1];
            float a[8] = {a0.x, a0.y, a0.z, a0.w, a1.x, a1.y, a1.z, a1.w};
            float b[8] = {b0.x, b0.y, b0.z, b0.w, b1.x, b1.y, b1.z, b1.w};
#pragma unroll
            for (int i = 0; i < 8; ++i)
#pragma unroll
                for (int j = 0; j < 8; ++j)
                    acc[i][j] = fmaf(a[i], b[j], acc[i][j]);
        }
    }

    // epilogue: add bias, write out
#pragma unroll
    for (int i = 0; i < 8; ++i) {
        float* orow = &out[(size_t)(m0 + tm + i) * DD + n0 + tn];
        float4 o0 = make_float4(acc[i][0] + bias[n0 + tn + 0],
                                acc[i][1] + bias[n0 + tn + 1],
                                acc[i][2] + bias[n0 + tn + 2],
                                acc[i][3] + bias[n0 + tn + 3]);
        float4 o1 = make_float4(acc[i][4] + bias[n0 + tn + 4],
                                acc[i][5] + bias[n0 + tn + 5],
                                acc[i][6] + bias[n0 + tn + 6],
                                acc[i][7] + bias[n0 + tn + 7]);
        *(float4*)&orow[0] = o0;
        *(float4*)&orow[4] = o1;
    }
}

// ---------------------------------------------------------------------------
// Kernel 2: flash attention with encoding biases.
// One CTA per 64 query rows. O[64][512] lives in SMEM. K/V streamed in
// 64-wide tiles (K,V are L2-resident: 32 MB total vs 126 MB L2).
// ---------------------------------------------------------------------------
#define SMEM_FLOATS (32768 /*Os*/ + 4096 /*Ss*/ + 8192 /*Ust*/ + 192 /*m,l,f*/)
#define SMEM_BYTES  (SMEM_FLOATS * 4)

__global__ __launch_bounds__(256, 1)
void flash_attn_kernel(const float* __restrict__ spatial,
                       const float* __restrict__ edge,
                       float* __restrict__ outp) {
    extern __shared__ float sm[];
    float* Os   = sm;                    // [64][512]
    float* Ss   = sm + 32768;            // [64][64]
    float* Ust  = sm + 32768 + 4096;     // staging: Qc(4096) + Kc(4096) | Vc(4096)
    float* mrow = Ust + 8192;            // [64]
    float* lrow = mrow + 64;             // [64]
    float* frow = lrow + 64;             // [64]

    float4* Os4       = (float4*)Os;
    const float4* Qc4 = (const float4*)Ust;
    const float4* Kc4 = (const float4*)(Ust + 4096);
    const float4* Vc4 = (const float4*)Ust;

    const int t   = threadIdx.x;
    const int tm4 = t >> 4;        // 0..15
    const int tm  = tm4 * 4;
    const int tn4 = t & 15;        // 0..15
    const int m0  = blockIdx.x * BR;

    const float scale = 0.044194173824159216f;  // 1/sqrt(512)

    // init O, m, l
    for (int idx = t; idx < 8192; idx += 256)
        Os4[idx] = make_float4(0.f, 0.f, 0.f, 0.f);
    if (t < 64) { mrow[t] = -INFINITY; lrow[t] = 0.0f; }
    __syncthreads();

    for (int j = 0; j < NN / BC; ++j) {
        const int n0 = j * BC;

        // ---- S = Q Kt (64x64), k-chunked through SMEM ----
        float sacc[4][4];
#pragma unroll
        for (int i = 0; i < 4; ++i)
#pragma unroll
            for (int jj = 0; jj < 4; ++jj) sacc[i][jj] = 0.0f;

        for (int kc = 0; kc < DD; kc += KCH) {
            __syncthreads();
#pragma unroll
            for (int i = 0; i < 4; ++i) {
                int f4 = t + i * 256;
                int mm = f4 & 63;
                int c4 = f4 >> 6;   // 0..15
                float4 qv = *(const float4*)&g_q[(size_t)(m0 + mm) * DD + kc + c4 * 4];
                float4 kv = *(const float4*)&g_k[(size_t)(n0 + mm) * DD + kc + c4 * 4];
                Ust[(c4 * 4 + 0) * 64 + mm] = qv.x;
                Ust[(c4 * 4 + 1) * 64 + mm] = qv.y;
                Ust[(c4 * 4 + 2) * 64 + mm] = qv.z;
                Ust[(c4 * 4 + 3) * 64 + mm] = qv.w;
                Ust[4096 + (c4 * 4 + 0) * 64 + mm] = kv.x;
                Ust[4096 + (c4 * 4 + 1) * 64 + mm] = kv.y;
                Ust[4096 + (c4 * 4 + 2) * 64 + mm] = kv.z;
                Ust[4096 + (c4 * 4 + 3) * 64 + mm] = kv.w;
            }
            __syncthreads();
#pragma unroll 8
            for (int kk = 0; kk < KCH; ++kk) {
                float4 a = Qc4[kk * 16 + tm4];
                float4 b = Kc4[kk * 16 + tn4];
                sacc[0][0] = fmaf(a.x, b.x, sacc[0][0]);
                sacc[0][1] = fmaf(a.x, b.y, sacc[0][1]);
                sacc[0][2] = fmaf(a.x, b.z, sacc[0][2]);
                sacc[0][3] = fmaf(a.x, b.w, sacc[0][3]);
                sacc[1][0] = fmaf(a.y, b.x, sacc[1][0]);
                sacc[1][1] = fmaf(a.y, b.y, sacc[1][1]);
                sacc[1][2] = fmaf(a.y, b.z, sacc[1][2]);
                sacc[1][3] = fmaf(a.y, b.w, sacc[1][3]);
                sacc[2][0] = fmaf(a.z, b.x, sacc[2][0]);
                sacc[2][1] = fmaf(a.z, b.y, sacc[2][1]);
                sacc[2][2] = fmaf(a.z, b.z, sacc[2][2]);
                sacc[2][3] = fmaf(a.z, b.w, sacc[2][3]);
                sacc[3][0] = fmaf(a.w, b.x, sacc[3][0]);
                sacc[3][1] = fmaf(a.w, b.y, sacc[3][1]);
                sacc[3][2] = fmaf(a.w, b.z, sacc[3][2]);
                sacc[3][3] = fmaf(a.w, b.w, sacc[3][3]);
            }
        }
        // store scaled scores to Ss
#pragma unroll
        for (int i = 0; i < 4; ++i) {
            ((float4*)Ss)[(tm + i) * 16 + tn4] =
                make_float4(sacc[i][0] * scale, sacc[i][1] * scale,
                            sacc[i][2] * scale, sacc[i][3] * scale);
        }
        __syncthreads();

        // ---- softmax over the tile (add encodings, online max/sum) ----
        {
            const int r  = t >> 2;          // 0..63
            const int c0 = (t & 3) * 16;    // 0..48
            const float* sprow = &spatial[(size_t)(m0 + r) * NN + n0 + c0];
            const float* edrow = &edge[(size_t)(m0 + r) * NN + n0 + c0];
            float vals[16];
            float mloc = -INFINITY;
#pragma unroll
            for (int c = 0; c < 16; c += 4) {
                float4 sp = *(const float4*)&sprow[c];
                float4 ed = *(const float4*)&edrow[c];
                float4 ss = *(const float4*)&Ss[r * 64 + c0 + c];
                vals[c + 0] = ss.x + sp.x + ed.x;
                vals[c + 1] = ss.y + sp.y + ed.y;
                vals[c + 2] = ss.z + sp.z + ed.z;
                vals[c + 3] = ss.w + sp.w + ed.w;
                mloc = fmaxf(mloc, fmaxf(fmaxf(vals[c], vals[c + 1]),
                                         fmaxf(vals[c + 2], vals[c + 3])));
            }
            mloc = fmaxf(mloc, __shfl_xor_sync(0xffffffffu, mloc, 1));
            mloc = fmaxf(mloc, __shfl_xor_sync(0xffffffffu, mloc, 2));
            float mold = mrow[r];
            float mnew = fmaxf(mold, mloc);
            float ssum = 0.0f;
#pragma unroll
            for (int c = 0; c < 16; c += 4) {
                float p0 = __expf(vals[c + 0] - mnew);
                float p1 = __expf(vals[c + 1] - mnew);
                float p2 = __expf(vals[c + 2] - mnew);
                float p3 = __expf(vals[c + 3] - mnew);
                *(float4*)&Ss[r * 64 + c0 + c] = make_float4(p0, p1, p2, p3);
                ssum += (p0 + p1) + (p2 + p3);
            }
            ssum += __shfl_xor_sync(0xffffffffu, ssum, 1);
            ssum += __shfl_xor_sync(0xffffffffu, ssum, 2);
            float f = (mold > -1e30f) ? __expf(mold - mnew) : 0.0f;
            if ((t & 3) == 0) {
                mrow[r] = mnew;
                lrow[r] = lrow[r] * f + ssum;
                frow[r] = f;
            }
        }
        __syncthreads();

        // ---- conditional O rescale ----
        for (int idx = t; idx < 8192; idx += 256) {
            float fr = frow[idx >> 7];
            if (fr != 1.0f) {
                float4 o = Os4[idx];
                o.x *= fr; o.y *= fr; o.z *= fr; o.w *= fr;
                Os4[idx] = o;
            }
        }
        __syncthreads();

        // ---- O += P @ V, d-chunked ----
        for (int dch = 0; dch < DD; dch += DCH) {
            __syncthreads();
#pragma unroll
            for (int i = 0; i < 4; ++i) {
                int f4 = t + i * 256;
                int kv = f4 >> 4;    // 0..63
                int c4 = f4 & 15;
                float4 vv = *(const float4*)&g_v[(size_t)(n0 + kv) * DD + dch + c4 * 4];
                ((float4*)Ust)[kv * 16 + c4] = vv;
            }
            __syncthreads();
            float oacc[4][4];
#pragma unroll
            for (int i = 0; i < 4; ++i)
#pragma unroll
                for (int jj = 0; jj < 4; ++jj) oacc[i][jj] = 0.0f;
#pragma unroll 8
            for (int kv = 0; kv < BC; ++kv) {
                float4 b = Vc4[kv * 16 + tn4];
                float a0 = Ss[(tm + 0) * 64 + kv];
                float a1 = Ss[(tm + 1) * 64 + kv];
                float a2 = Ss[(tm + 2) * 64 + kv];
                float a3 = Ss[(tm + 3) * 64 + kv];
                oacc[0][0] = fmaf(a0, b.x, oacc[0][0]);
                oacc[0][1] = fmaf(a0, b.y, oacc[0][1]);
                oacc[0][2] = fmaf(a0, b.z, oacc[0][2]);
                oacc[0][3] = fmaf(a0, b.w, oacc[0][3]);
                oacc[1][0] = fmaf(a1, b.x, oacc[1][0]);
                oacc[1][1] = fmaf(a1, b.y, oacc[1][1]);
                oacc[1][2] = fmaf(a1, b.z, oacc[1][2]);
                oacc[1][3] = fmaf(a1, b.w, oacc[1][3]);
                oacc[2][0] = fmaf(a2, b.x, oacc[2][0]);
                oacc[2][1] = fmaf(a2, b.y, oacc[2][1]);
                oacc[2][2] = fmaf(a2, b.z, oacc[2][2]);
                oacc[2][3] = fmaf(a2, b.w, oacc[2][3]);
                oacc[3][0] = fmaf(a3, b.x, oacc[3][0]);
                oacc[3][1] = fmaf(a3, b.y, oacc[3][1]);
                oacc[3][2] = fmaf(a3, b.z, oacc[3][2]);
                oacc[3][3] = fmaf(a3, b.w, oacc[3][3]);
            }
#pragma unroll
            for (int i = 0; i < 4; ++i) {
                int oi = (tm + i) * 128 + (dch >> 2) + tn4;
                float4 o = Os4[oi];
                o.x += oacc[i][0];
                o.y += oacc[i][1];
                o.z += oacc[i][2];
                o.w += oacc[i][3];
                Os4[oi] = o;
            }
        }
    }

    // ---- finalize: divide by l and write ----
    __syncthreads();
    float4* out4 = (float4*)outp;
    for (int idx = t; idx < 8192; idx += 256) {
        int r2 = idx >> 7;
        float inv = 1.0f / lrow[r2];
        float4 o = Os4[idx];
        o.x *= inv; o.y *= inv; o.z *= inv; o.w *= inv;
        out4[(size_t)(m0 + r2) * 128 + (idx & 127)] = o;
    }
}

// ---------------------------------------------------------------------------
extern "C" void kernel_launch(void* const* d_in, const int* in_sizes, int n_in,
                              void* d_out, int out_size) {
    const float* x       = (const float*)d_in[0];
    const float* spatial = (const float*)d_in[1];
    const float* edge    = (const float*)d_in[2];
    const float* Wq      = (const float*)d_in[3];
    const float* bq      = (const float*)d_in[4];
    const float* Wk      = (const float*)d_in[5];
    const float* bk      = (const float*)d_in[6];
    const float* Wv      = (const float*)d_in[7];
    const float* bv      = (const float*)d_in[8];
    float* out           = (float*)d_out;

    static bool attr_set = false;
    if (!attr_set) {
        cudaFuncSetAttribute(flash_attn_kernel,
                             cudaFuncAttributeMaxDynamicSharedMemorySize,
                             SMEM_BYTES);
        attr_set = true;
    }

    // Kernel 1: Q/K/V projections
    dim3 pgrid(DD / 128, NN / 128, 3);
    qkv_proj_kernel<<<pgrid, 256>>>(x, Wq, bq, Wk, bk, Wv, bv);

    // Kernel 2: flash attention
    flash_attn_kernel<<<NN / BR, 256, SMEM_BYTES>>>(spatial, edge, out);
}

// round 4
// speedup vs baseline: 5.5143x; 3.5058x over previous
#include <cuda_runtime.h>
#include <cuda_bf16.h>
#include <stdint.h>
#include <math.h>

#define NN 8192
#define DD 512
#define SCALE 0.044194173824159216f

// ----------------- device scratch (allocation-free rule) -----------------
__device__ float g_v[NN * DD];
__device__ __nv_bfloat16 gq_hi[NN * DD], gq_lo[NN * DD];
__device__ __nv_bfloat16 gk_hi[NN * DD], gk_lo[NN * DD];
__device__ __nv_bfloat16 gvt_hi[DD * NN], gvt_lo[DD * NN];
__device__ __nv_bfloat16 gP_hi[(size_t)NN * NN], gP_lo[(size_t)NN * NN];
__device__ float g_lpart[64 * NN];
__device__ float g_l[NN];

// ----------------- helpers -----------------
__device__ __forceinline__ uint32_t smem_u32(const void* p) {
    uint32_t a;
    asm("{ .reg .u64 t; cvta.to.shared.u64 t, %1; cvt.u32.u64 %0, t; }" : "=r"(a) : "l"(p));
    return a;
}
__device__ __forceinline__ uint32_t pack2(__nv_bfloat16 a, __nv_bfloat16 b) {
    return (uint32_t)__bfloat16_as_ushort(a) | ((uint32_t)__bfloat16_as_ushort(b) << 16);
}
__device__ __forceinline__ void cpa16(uint32_t dst, const void* src) {
    asm volatile("cp.async.cg.shared.global [%0], [%1], 16;" :: "r"(dst), "l"(src));
}
__device__ __forceinline__ void cpa_commit() {
    asm volatile("cp.async.commit_group;" ::: "memory");
}
__device__ __forceinline__ void ldsm4(uint32_t* r, uint32_t addr) {
    asm volatile("ldmatrix.sync.aligned.m8n8.x4.shared.b16 {%0,%1,%2,%3}, [%4];"
                 : "=r"(r[0]), "=r"(r[1]), "=r"(r[2]), "=r"(r[3]) : "r"(addr));
}
__device__ __forceinline__ void mma16816(float* c, const uint32_t* a, const uint32_t* b) {
    asm volatile(
        "mma.sync.aligned.m16n8k16.row.col.f32.bf16.bf16.f32 "
        "{%0,%1,%2,%3}, {%4,%5,%6,%7}, {%8,%9}, {%0,%1,%2,%3};"
        : "+f"(c[0]), "+f"(c[1]), "+f"(c[2]), "+f"(c[3])
        : "r"(a[0]), "r"(a[1]), "r"(a[2]), "r"(a[3]), "r"(b[0]), "r"(b[1]));
}

// ---------------------------------------------------------------------------
// QKV projection (FFMA SGEMM). z=0: Q -> bf16 hi/lo. z=1: K -> hi/lo. z=2: V fp32.
// ---------------------------------------------------------------------------
__global__ __launch_bounds__(256, 2)
void qkv_proj_kernel(const float* __restrict__ x,
                     const float* __restrict__ Wq, const float* __restrict__ bq,
                     const float* __restrict__ Wk, const float* __restrict__ bk,
                     const float* __restrict__ Wv, const float* __restrict__ bv) {
    __shared__ float As[8 * 128];
    __shared__ float Bs[8 * 128];
    const float* W; const float* bias;
    if (blockIdx.z == 0)      { W = Wq; bias = bq; }
    else if (blockIdx.z == 1) { W = Wk; bias = bk; }
    else                      { W = Wv; bias = bv; }

    const int t = threadIdx.x;
    const int m0 = blockIdx.y * 128, n0 = blockIdx.x * 128;
    const int tm = (t >> 4) * 8, tn = (t & 15) * 8;
    float acc[8][8];
#pragma unroll
    for (int i = 0; i < 8; ++i)
#pragma unroll
        for (int j = 0; j < 8; ++j) acc[i][j] = 0.0f;

    const int mload = t >> 1, k4 = (t & 1) * 4;
    const float4* As4 = (const float4*)As;
    const float4* Bs4 = (const float4*)Bs;

    for (int k0 = 0; k0 < DD; k0 += 8) {
        float4 av  = *(const float4*)&x[(size_t)(m0 + mload) * DD + k0 + k4];
        float4 bv4 = *(const float4*)&W[(size_t)(n0 + mload) * DD + k0 + k4];
        __syncthreads();
#pragma unroll
        for (int q = 0; q < 4; ++q) {
            As[(k4 + q) * 128 + mload] = ((const float*)&av)[q];
            Bs[(k4 + q) * 128 + mload] = ((const float*)&bv4)[q];
        }
        __syncthreads();
#pragma unroll
        for (int kk = 0; kk < 8; ++kk) {
            float4 a0 = As4[kk * 32 + (t >> 4) * 2];
            float4 a1 = As4[kk * 32 + (t >> 4) * 2 + 1];
            float4 b0 = Bs4[kk * 32 + (t & 15) * 2];
            float4 b1 = Bs4[kk * 32 + (t & 15) * 2 + 1];
            float a[8] = {a0.x, a0.y, a0.z, a0.w, a1.x, a1.y, a1.z, a1.w};
            float b[8] = {b0.x, b0.y, b0.z, b0.w, b1.x, b1.y, b1.z, b1.w};
#pragma unroll
            for (int i = 0; i < 8; ++i)
#pragma unroll
                for (int j = 0; j < 8; ++j)
                    acc[i][j] = fmaf(a[i], b[j], acc[i][j]);
        }
    }
    float bs[8];
#pragma unroll
    for (int j = 0; j < 8; ++j) bs[j] = bias[n0 + tn + j];

    if (blockIdx.z == 2) {
#pragma unroll
        for (int i = 0; i < 8; ++i) {
            float* orow = &g_v[(size_t)(m0 + tm + i) * DD + n0 + tn];
#pragma unroll
            for (int j = 0; j < 8; j += 4)
                *(float4*)&orow[j] = make_float4(acc[i][j] + bs[j], acc[i][j + 1] + bs[j + 1],
                                                 acc[i][j + 2] + bs[j + 2], acc[i][j + 3] + bs[j + 3]);
        }
    } else {
        __nv_bfloat16* oh = blockIdx.z ? gk_hi : gq_hi;
        __nv_bfloat16* ol = blockIdx.z ? gk_lo : gq_lo;
#pragma unroll
        for (int i = 0; i < 8; ++i) {
            uint32_t hw[4], lw[4];
#pragma unroll
            for (int p = 0; p < 4; ++p) {
                float v0 = acc[i][2 * p] + bs[2 * p];
                float v1 = acc[i][2 * p + 1] + bs[2 * p + 1];
                __nv_bfloat16 h0 = __float2bfloat16(v0), h1 = __float2bfloat16(v1);
                hw[p] = pack2(h0, h1);
                lw[p] = pack2(__float2bfloat16(v0 - __bfloat162float(h0)),
                              __float2bfloat16(v1 - __bfloat162float(h1)));
            }
            size_t o = (size_t)(m0 + tm + i) * DD + n0 + tn;
            *(uint4*)(oh + o) = make_uint4(hw[0], hw[1], hw[2], hw[3]);
            *(uint4*)(ol + o) = make_uint4(lw[0], lw[1], lw[2], lw[3]);
        }
    }
}

// ---------------------------------------------------------------------------
// V transpose + bf16 split: gvt[d][j] from g_v[j][d]
// ---------------------------------------------------------------------------
__global__ __launch_bounds__(256, 4)
void vtrans_kernel() {
    __shared__ float ts[32][33];
    int j0 = blockIdx.x * 32, d0 = blockIdx.y * 32;
    int tx = threadIdx.x & 31, ty = threadIdx.x >> 5;
#pragma unroll
    for (int i = 0; i < 4; ++i)
        ts[ty + 8 * i][tx] = g_v[(size_t)(j0 + ty + 8 * i) * DD + d0 + tx];
    __syncthreads();
#pragma unroll
    for (int i = 0; i < 4; ++i) {
        float v = ts[tx][ty + 8 * i];
        __nv_bfloat16 h = __float2bfloat16(v);
        __nv_bfloat16 l = __float2bfloat16(v - __bfloat162float(h));
        size_t o = (size_t)(d0 + ty + 8 * i) * NN + j0 + tx;
        gvt_hi[o] = h;
        gvt_lo[o] = l;
    }
}

// ---------------------------------------------------------------------------
// Pass 1: P = exp(scale*Q@K^T + sp + ed) via mma.sync; stores P hi/lo bf16 and
// per-CTA-column row-sum partials. CTA tile 128x128, warps 2x4 (warp 64x32).
// SMEM rows padded to 80B: ldmatrix conflict-free.
// ---------------------------------------------------------------------------
__global__ __launch_bounds__(256, 2)
void pass1_kernel(const float* __restrict__ sp, const float* __restrict__ ed) {
    __shared__ __align__(128) char smem[43008];
    float* smem_l = (float*)(smem + 40960);
    const int t = threadIdx.x, wid = t >> 5, lane = t & 31;
    const int m0 = blockIdx.y * 128, n0 = blockIdx.x * 128;
    const uint32_t sb = smem_u32(smem);
    const int wr = wid >> 2, wc = wid & 3;

    float acc[4][4][4];
#pragma unroll
    for (int mi = 0; mi < 4; ++mi)
#pragma unroll
        for (int ni = 0; ni < 4; ++ni)
#pragma unroll
            for (int q = 0; q < 4; ++q) acc[mi][ni][q] = 0.0f;

    const int sr = t >> 2, sc = t & 3;   // stage: row pair index base, 16B chunk

#define P1_STAGE(cc, buf)                                                          \
    {                                                                              \
        int term_ = (cc) >> 4, kk_ = ((cc) & 15) * 32;                             \
        const __nv_bfloat16* Aa_ = (term_ == 2) ? gq_lo : gq_hi;                   \
        const __nv_bfloat16* Bb_ = (term_ == 1) ? gk_lo : gk_hi;                   \
        uint32_t da_ = sb + (buf) * 10240, db_ = sb + 20480 + (buf) * 10240;       \
        const __nv_bfloat16* As_ = Aa_ + (size_t)m0 * DD + kk_;                    \
        const __nv_bfloat16* Bs_ = Bb_ + (size_t)n0 * DD + kk_;                    \
        _Pragma("unroll")                                                          \
        for (int i_ = 0; i_ < 2; ++i_) {                                           \
            int r_ = sr + i_ * 64;                                                 \
            cpa16(da_ + r_ * 80 + sc * 16, As_ + (size_t)r_ * DD + sc * 8);        \
            cpa16(db_ + r_ * 80 + sc * 16, Bs_ + (size_t)r_ * DD + sc * 8);        \
        }                                                                          \
        cpa_commit();                                                              \
    }

    P1_STAGE(0, 0);
    const uint32_t aOff = (uint32_t)(wr * 64 + (lane & 15)) * 80 + (lane >> 4) * 16;
    const uint32_t bOff = (uint32_t)(wc * 32 + (lane & 7) + ((lane >> 4) & 1) * 8) * 80 +
                          ((lane >> 3) & 1) * 16;

    for (int cc = 0; cc < 48; ++cc) {
        if (cc < 47) {
            P1_STAGE(cc + 1, (cc + 1) & 1);
            asm volatile("cp.async.wait_group 1;" ::: "memory");
        } else {
            asm volatile("cp.async.wait_group 0;" ::: "memory");
        }
        __syncthreads();
        uint32_t sA = sb + (cc & 1) * 10240, sB = sb + 20480 + (cc & 1) * 10240;
#pragma unroll
        for (int kq = 0; kq < 2; ++kq) {
            uint32_t a[4][4];
#pragma unroll
            for (int mi = 0; mi < 4; ++mi)
                ldsm4(a[mi], sA + aOff + mi * 1280 + kq * 32);
#pragma unroll
            for (int nj = 0; nj < 2; ++nj) {
                uint32_t b[4];
                ldsm4(b, sB + bOff + nj * 1280 + kq * 32);
#pragma unroll
                for (int mi = 0; mi < 4; ++mi) {
                    mma16816(acc[mi][nj * 2], a[mi], b);
                    mma16816(acc[mi][nj * 2 + 1], a[mi], b + 2);
                }
            }
        }
        __syncthreads();
    }

    // epilogue: bias add, exp, split-store P, row sums
#pragma unroll
    for (int mi = 0; mi < 4; ++mi) {
#pragma unroll
        for (int h = 0; h < 2; ++h) {
            int rloc = wr * 64 + mi * 16 + (lane >> 2) + h * 8;
            size_t rb = (size_t)(m0 + rloc) * NN;
            float rs = 0.0f;
#pragma unroll
            for (int ni = 0; ni < 4; ++ni) {
                int col = n0 + wc * 32 + ni * 8 + (lane & 3) * 2;
                float2 s2 = *(const float2*)(sp + rb + col);
                float2 e2 = *(const float2*)(ed + rb + col);
                float p0 = __expf(acc[mi][ni][h * 2] * SCALE + s2.x + e2.x);
                float p1 = __expf(acc[mi][ni][h * 2 + 1] * SCALE + s2.y + e2.y);
                __nv_bfloat16 h0 = __float2bfloat16(p0), h1 = __float2bfloat16(p1);
                *(uint32_t*)(gP_hi + rb + col) = pack2(h0, h1);
                *(uint32_t*)(gP_lo + rb + col) =
                    pack2(__float2bfloat16(p0 - __bfloat162float(h0)),
                          __float2bfloat16(p1 - __bfloat162float(h1)));
                rs += p0 + p1;
            }
            rs += __shfl_xor_sync(0xffffffffu, rs, 1);
            rs += __shfl_xor_sync(0xffffffffu, rs, 2);
            if ((lane & 3) == 0) smem_l[rloc * 4 + wc] = rs;
        }
    }
    __syncthreads();
    if (t < 128) {
        float s = smem_l[t * 4] + smem_l[t * 4 + 1] + smem_l[t * 4 + 2] + smem_l[t * 4 + 3];
        g_lpart[(size_t)blockIdx.x * NN + m0 + t] = s;
    }
}

// ---------------------------------------------------------------------------
// l reduce: g_l[row] = sum over 64 column-block partials (deterministic)
// ---------------------------------------------------------------------------
__global__ void lreduce_kernel() {
    int r = blockIdx.x * 256 + threadIdx.x;
    float s = 0.0f;
    for (int b = 0; b < 64; ++b) s += g_lpart[(size_t)b * NN + r];
    g_l[r] = s;
}

// ---------------------------------------------------------------------------
// Pass 2: O = (Ph*Vh + Ph*Vl + Pl*Vh) / l. CTA 128x256, warps 4x2 (warp 32x128).
// B operand = gvt (V^T, [d][keys]) staged 256x32 per chunk.
// ---------------------------------------------------------------------------
__global__ __launch_bounds__(256, 1)
void pass2_kernel(float* __restrict__ outp) {
    extern __shared__ char smem[];
    const int t = threadIdx.x, wid = t >> 5, lane = t & 31;
    const int n0 = blockIdx.x * 256, m0 = blockIdx.y * 128;
    const uint32_t sb = smem_u32(smem);
    const int wr = wid >> 1, wc = wid & 1;

    float acc[2][16][4];
#pragma unroll
    for (int mi = 0; mi < 2; ++mi)
#pragma unroll
        for (int ni = 0; ni < 16; ++ni)
#pragma unroll
            for (int q = 0; q < 4; ++q) acc[mi][ni][q] = 0.0f;

    const int sr = t >> 2, sc = t & 3;

#define P2_STAGE(cc, buf)                                                            \
    {                                                                                \
        int term_ = (cc) >> 8, kk_ = ((cc) & 255) * 32;                              \
        const __nv_bfloat16* Aa_ = (term_ == 2) ? gP_lo : gP_hi;                     \
        const __nv_bfloat16* Bb_ = (term_ == 1) ? gvt_lo : gvt_hi;                   \
        uint32_t da_ = sb + (buf) * 10240, db_ = sb + 20480 + (buf) * 20480;         \
        const __nv_bfloat16* As_ = Aa_ + (size_t)m0 * NN + kk_;                      \
        const __nv_bfloat16* Bs_ = Bb_ + (size_t)n0 * NN + kk_;                      \
        _Pragma("unroll")                                                            \
        for (int i_ = 0; i_ < 2; ++i_) {                                             \
            int r_ = sr + i_ * 64;                                                   \
            cpa16(da_ + r_ * 80 + sc * 16, As_ + (size_t)r_ * NN + sc * 8);          \
        }                                                                            \
        _Pragma("unroll")                                                            \
        for (int i_ = 0; i_ < 4; ++i_) {                                             \
            int r_ = sr + i_ * 64;                                                   \
            cpa16(db_ + r_ * 80 + sc * 16, Bs_ + (size_t)r_ * NN + sc * 8);          \
        }                                                                            \
        cpa_commit();                                                                \
    }

    P2_STAGE(0, 0);
    const uint32_t aOff = (uint32_t)(wr * 32 + (lane & 15)) * 80 + (lane >> 4) * 16;
    const uint32_t bOff = (uint32_t)(wc * 128 + (lane & 7) + ((lane >> 4) & 1) * 8) * 80 +
                          ((lane >> 3) & 1) * 16;

    for (int cc = 0; cc < 768; ++cc) {
        if (cc < 767) {
            P2_STAGE(cc + 1, (cc + 1) & 1);
            asm volatile("cp.async.wait_group 1;" ::: "memory");
        } else {
            asm volatile("cp.async.wait_group 0;" ::: "memory");
        }
        __syncthreads();
        uint32_t sA = sb + (cc & 1) * 10240, sB = sb + 20480 + (cc & 1) * 20480;
#pragma unroll
        for (int kq = 0; kq < 2; ++kq) {
            uint32_t a[2][4];
            ldsm4(a[0], sA + aOff + kq * 32);
            ldsm4(a[1], sA + aOff + 1280 + kq * 32);
#pragma unroll
            for (int nj = 0; nj < 8; ++nj) {
                uint32_t b[4];
                ldsm4(b, sB + bOff + nj * 1280 + kq * 32);
                mma16816(acc[0][nj * 2], a[0], b);
                mma16816(acc[0][nj * 2 + 1], a[0], b + 2);
                mma16816(acc[1][nj * 2], a[1], b);
                mma16816(acc[1][nj * 2 + 1], a[1], b + 2);
            }
        }
        __syncthreads();
    }

    // epilogue: divide by l, store
#pragma unroll
    for (int mi = 0; mi < 2; ++mi) {
#pragma unroll
        for (int h = 0; h < 2; ++h) {
            int row = m0 + wr * 32 + mi * 16 + (lane >> 2) + h * 8;
            float inv = 1.0f / g_l[row];
#pragma unroll
            for (int ni = 0; ni < 16; ++ni) {
                int col = n0 + wc * 128 + ni * 8 + (lane & 3) * 2;
                float2 o;
                o.x = acc[mi][ni][h * 2] * inv;
                o.y = acc[mi][ni][h * 2 + 1] * inv;
                *(float2*)(outp + (size_t)row * DD + col) = o;
            }
        }
    }
}

// ---------------------------------------------------------------------------
extern "C" void kernel_launch(void* const* d_in, const int* in_sizes, int n_in,
                              void* d_out, int out_size) {
    const float* x       = (const float*)d_in[0];
    const float* spatial = (const float*)d_in[1];
    const float* edge    = (const float*)d_in[2];
    const float* Wq      = (const float*)d_in[3];
    const float* bq      = (const float*)d_in[4];
    const float* Wk      = (const float*)d_in[5];
    const float* bk      = (const float*)d_in[6];
    const float* Wv      = (const float*)d_in[7];
    const float* bv      = (const float*)d_in[8];
    float* out           = (float*)d_out;

    cudaFuncSetAttribute(pass2_kernel, cudaFuncAttributeMaxDynamicSharedMemorySize, 61440);

    dim3 pgrid(DD / 128, NN / 128, 3);
    qkv_proj_kernel<<<pgrid, 256>>>(x, Wq, bq, Wk, bk, Wv, bv);
    vtrans_kernel<<<dim3(NN / 32, DD / 32), 256>>>();
    pass1_kernel<<<dim3(64, 64), 256>>>(spatial, edge);
    lreduce_kernel<<<32, 256>>>();
    pass2_kernel<<<dim3(2, 64), 256, 61440>>>(out);
}

// round 5
// speedup vs baseline: 5.8813x; 1.0666x over previous
#include <cuda_runtime.h>
#include <cuda_bf16.h>
#include <stdint.h>
#include <math.h>

#define NN 8192
#define DD 512
#define SCALE 0.044194173824159216f

// ----------------- device scratch (allocation-free rule) -----------------
__device__ float g_v[NN * DD];
__device__ __nv_bfloat16 gx_hi[NN * DD], gx_lo[NN * DD];
__device__ __nv_bfloat16 gw_hi[3 * DD * DD], gw_lo[3 * DD * DD];
__device__ __nv_bfloat16 gq_hi[NN * DD], gq_lo[NN * DD];
__device__ __nv_bfloat16 gk_hi[NN * DD], gk_lo[NN * DD];
__device__ __nv_bfloat16 gvt_hi[DD * NN], gvt_lo[DD * NN];
__device__ __nv_bfloat16 gP_hi[(size_t)NN * NN], gP_lo[(size_t)NN * NN];
__device__ float g_lpart[64 * NN];
__device__ float g_l[NN];

// ----------------- helpers -----------------
__device__ __forceinline__ uint32_t smem_u32(const void* p) {
    uint32_t a;
    asm("{ .reg .u64 t; cvta.to.shared.u64 t, %1; cvt.u32.u64 %0, t; }" : "=r"(a) : "l"(p));
    return a;
}
__device__ __forceinline__ uint32_t pack2(__nv_bfloat16 a, __nv_bfloat16 b) {
    return (uint32_t)__bfloat16_as_ushort(a) | ((uint32_t)__bfloat16_as_ushort(b) << 16);
}
__device__ __forceinline__ void cpa16(uint32_t dst, const void* src) {
    asm volatile("cp.async.cg.shared.global [%0], [%1], 16;" :: "r"(dst), "l"(src));
}
__device__ __forceinline__ void cpa_commit() {
    asm volatile("cp.async.commit_group;" ::: "memory");
}
__device__ __forceinline__ void ldsm4(uint32_t* r, uint32_t addr) {
    asm volatile("ldmatrix.sync.aligned.m8n8.x4.shared.b16 {%0,%1,%2,%3}, [%4];"
                 : "=r"(r[0]), "=r"(r[1]), "=r"(r[2]), "=r"(r[3]) : "r"(addr));
}
__device__ __forceinline__ void mma16816(float* c, const uint32_t* a, const uint32_t* b) {
    asm volatile(
        "mma.sync.aligned.m16n8k16.row.col.f32.bf16.bf16.f32 "
        "{%0,%1,%2,%3}, {%4,%5,%6,%7}, {%8,%9}, {%0,%1,%2,%3};"
        : "+f"(c[0]), "+f"(c[1]), "+f"(c[2]), "+f"(c[3])
        : "r"(a[0]), "r"(a[1]), "r"(a[2]), "r"(a[3]), "r"(b[0]), "r"(b[1]));
}

// ---------------------------------------------------------------------------
// Split x and Wq/Wk/Wv into bf16 hi/lo (float4-vectorized)
// ---------------------------------------------------------------------------
__global__ __launch_bounds__(256)
void split_kernel(const float* __restrict__ x, const float* __restrict__ Wq,
                  const float* __restrict__ Wk, const float* __restrict__ Wv) {
    int i4 = blockIdx.x * 256 + threadIdx.x;
    const float4* src;
    uint2 *oh, *ol;
    int off;
    if (i4 < NN * DD / 4) {
        src = (const float4*)x; oh = (uint2*)gx_hi; ol = (uint2*)gx_lo; off = i4;
    } else {
        int r = i4 - NN * DD / 4;
        int wi = r >> 16, rr = r & 65535;
        const float* w = (wi == 0) ? Wq : (wi == 1) ? Wk : Wv;
        src = (const float4*)w; off = rr;
        oh = (uint2*)(gw_hi + (size_t)wi * DD * DD);
        ol = (uint2*)(gw_lo + (size_t)wi * DD * DD);
    }
    float4 v = src[off];
    __nv_bfloat16 h0 = __float2bfloat16(v.x), h1 = __float2bfloat16(v.y);
    __nv_bfloat16 h2 = __float2bfloat16(v.z), h3 = __float2bfloat16(v.w);
    uint2 H, L;
    H.x = pack2(h0, h1);
    H.y = pack2(h2, h3);
    L.x = pack2(__float2bfloat16(v.x - __bfloat162float(h0)),
                __float2bfloat16(v.y - __bfloat162float(h1)));
    L.y = pack2(__float2bfloat16(v.z - __bfloat162float(h2)),
                __float2bfloat16(v.w - __bfloat162float(h3)));
    oh[off] = H;
    ol[off] = L;
}

// ---------------------------------------------------------------------------
// Tensor-core QKV projection: y = x @ W^T + b via 3-term bf16 mma.sync.
// CTA tile 128x128, warps 2x4 (warp 64x32). 48 chunks = 3 terms x 16 (K=512/32).
// z=0: Q -> bf16 hi/lo. z=1: K -> hi/lo. z=2: V fp32.
// ---------------------------------------------------------------------------
__global__ __launch_bounds__(256, 2)
void proj_kernel(const float* __restrict__ bq, const float* __restrict__ bk,
                 const float* __restrict__ bv) {
    __shared__ __align__(128) char smem[40960];
    const int t = threadIdx.x, wid = t >> 5, lane = t & 31;
    const int z = blockIdx.z;
    const int m0 = blockIdx.y * 128, n0 = blockIdx.x * 128;
    const uint32_t sb = smem_u32(smem);
    const int wr = wid >> 2, wc = wid & 3;
    const __nv_bfloat16* WHz = gw_hi + (size_t)z * DD * DD;
    const __nv_bfloat16* WLz = gw_lo + (size_t)z * DD * DD;

    float acc[4][4][4];
#pragma unroll
    for (int mi = 0; mi < 4; ++mi)
#pragma unroll
        for (int ni = 0; ni < 4; ++ni)
#pragma unroll
            for (int q = 0; q < 4; ++q) acc[mi][ni][q] = 0.0f;

    const int sr = t >> 2, sc = t & 3;

#define PJ_STAGE(cc, buf)                                                          \
    {                                                                              \
        int term_ = (cc) >> 4, kk_ = ((cc) & 15) * 32;                             \
        const __nv_bfloat16* Aa_ = (term_ == 2) ? gx_lo : gx_hi;                   \
        const __nv_bfloat16* Bb_ = (term_ == 1) ? WLz : WHz;                       \
        uint32_t da_ = sb + (buf) * 10240, db_ = sb + 20480 + (buf) * 10240;       \
        const __nv_bfloat16* As_ = Aa_ + (size_t)m0 * DD + kk_;                    \
        const __nv_bfloat16* Bs_ = Bb_ + (size_t)n0 * DD + kk_;                    \
        _Pragma("unroll")                                                          \
        for (int i_ = 0; i_ < 2; ++i_) {                                           \
            int r_ = sr + i_ * 64;                                                 \
            cpa16(da_ + r_ * 80 + sc * 16, As_ + (size_t)r_ * DD + sc * 8);        \
            cpa16(db_ + r_ * 80 + sc * 16, Bs_ + (size_t)r_ * DD + sc * 8);        \
        }                                                                          \
        cpa_commit();                                                              \
    }

    PJ_STAGE(0, 0);
    const uint32_t aOff = (uint32_t)(wr * 64 + (lane & 15)) * 80 + (lane >> 4) * 16;
    const uint32_t bOff = (uint32_t)(wc * 32 + (lane & 7) + ((lane >> 4) & 1) * 8) * 80 +
                          ((lane >> 3) & 1) * 16;

    for (int cc = 0; cc < 48; ++cc) {
        if (cc < 47) {
            PJ_STAGE(cc + 1, (cc + 1) & 1);
            asm volatile("cp.async.wait_group 1;" ::: "memory");
        } else {
            asm volatile("cp.async.wait_group 0;" ::: "memory");
        }
        __syncthreads();
        uint32_t sA = sb + (cc & 1) * 10240, sB = sb + 20480 + (cc & 1) * 10240;
#pragma unroll
        for (int kq = 0; kq < 2; ++kq) {
            uint32_t a[4][4];
#pragma unroll
            for (int mi = 0; mi < 4; ++mi)
                ldsm4(a[mi], sA + aOff + mi * 1280 + kq * 32);
#pragma unroll
            for (int nj = 0; nj < 2; ++nj) {
                uint32_t b[4];
                ldsm4(b, sB + bOff + nj * 1280 + kq * 32);
#pragma unroll
                for (int mi = 0; mi < 4; ++mi) {
                    mma16816(acc[mi][nj * 2], a[mi], b);
                    mma16816(acc[mi][nj * 2 + 1], a[mi], b + 2);
                }
            }
        }
        __syncthreads();
    }

    const float* bias = (z == 0) ? bq : (z == 1) ? bk : bv;
#pragma unroll
    for (int mi = 0; mi < 4; ++mi) {
#pragma unroll
        for (int h = 0; h < 2; ++h) {
            int row = m0 + wr * 64 + mi * 16 + (lane >> 2) + h * 8;
#pragma unroll
            for (int ni = 0; ni < 4; ++ni) {
                int col = n0 + wc * 32 + ni * 8 + (lane & 3) * 2;
                float2 bb = *(const float2*)(bias + col);
                float v0 = acc[mi][ni][h * 2] + bb.x;
                float v1 = acc[mi][ni][h * 2 + 1] + bb.y;
                if (z == 2) {
                    *(float2*)(g_v + (size_t)row * DD + col) = make_float2(v0, v1);
                } else {
                    __nv_bfloat16* oh = z ? gk_hi : gq_hi;
                    __nv_bfloat16* ol = z ? gk_lo : gq_lo;
                    __nv_bfloat16 h0 = __float2bfloat16(v0), h1 = __float2bfloat16(v1);
                    *(uint32_t*)(oh + (size_t)row * DD + col) = pack2(h0, h1);
                    *(uint32_t*)(ol + (size_t)row * DD + col) =
                        pack2(__float2bfloat16(v0 - __bfloat162float(h0)),
                              __float2bfloat16(v1 - __bfloat162float(h1)));
                }
            }
        }
    }
}

// ---------------------------------------------------------------------------
// V transpose + bf16 split: gvt[d][j] from g_v[j][d]
// ---------------------------------------------------------------------------
__global__ __launch_bounds__(256, 4)
void vtrans_kernel() {
    __shared__ float ts[32][33];
    int j0 = blockIdx.x * 32, d0 = blockIdx.y * 32;
    int tx = threadIdx.x & 31, ty = threadIdx.x >> 5;
#pragma unroll
    for (int i = 0; i < 4; ++i)
        ts[ty + 8 * i][tx] = g_v[(size_t)(j0 + ty + 8 * i) * DD + d0 + tx];
    __syncthreads();
#pragma unroll
    for (int i = 0; i < 4; ++i) {
        float v = ts[tx][ty + 8 * i];
        __nv_bfloat16 h = __float2bfloat16(v);
        __nv_bfloat16 l = __float2bfloat16(v - __bfloat162float(h));
        size_t o = (size_t)(d0 + ty + 8 * i) * NN + j0 + tx;
        gvt_hi[o] = h;
        gvt_lo[o] = l;
    }
}

// ---------------------------------------------------------------------------
// Pass 1: P = exp(scale*Q@K^T + sp + ed); stores P hi/lo bf16 and per-CTA
// row-sum partials. CTA tile 128x128, warps 2x4 (warp 64x32).
// ---------------------------------------------------------------------------
__global__ __launch_bounds__(256, 2)
void pass1_kernel(const float* __restrict__ sp, const float* __restrict__ ed) {
    __shared__ __align__(128) char smem[43008];
    float* smem_l = (float*)(smem + 40960);
    const int t = threadIdx.x, wid = t >> 5, lane = t & 31;
    const int m0 = blockIdx.y * 128, n0 = blockIdx.x * 128;
    const uint32_t sb = smem_u32(smem);
    const int wr = wid >> 2, wc = wid & 3;

    float acc[4][4][4];
#pragma unroll
    for (int mi = 0; mi < 4; ++mi)
#pragma unroll
        for (int ni = 0; ni < 4; ++ni)
#pragma unroll
            for (int q = 0; q < 4; ++q) acc[mi][ni][q] = 0.0f;

    const int sr = t >> 2, sc = t & 3;

#define P1_STAGE(cc, buf)                                                          \
    {                                                                              \
        int term_ = (cc) >> 4, kk_ = ((cc) & 15) * 32;                             \
        const __nv_bfloat16* Aa_ = (term_ == 2) ? gq_lo : gq_hi;                   \
        const __nv_bfloat16* Bb_ = (term_ == 1) ? gk_lo : gk_hi;                   \
        uint32_t da_ = sb + (buf) * 10240, db_ = sb + 20480 + (buf) * 10240;       \
        const __nv_bfloat16* As_ = Aa_ + (size_t)m0 * DD + kk_;                    \
        const __nv_bfloat16* Bs_ = Bb_ + (size_t)n0 * DD + kk_;                    \
        _Pragma("unroll")                                                          \
        for (int i_ = 0; i_ < 2; ++i_) {                                           \
            int r_ = sr + i_ * 64;                                                 \
            cpa16(da_ + r_ * 80 + sc * 16, As_ + (size_t)r_ * DD + sc * 8);        \
            cpa16(db_ + r_ * 80 + sc * 16, Bs_ + (size_t)r_ * DD + sc * 8);        \
        }                                                                          \
        cpa_commit();                                                              \
    }

    P1_STAGE(0, 0);
    const uint32_t aOff = (uint32_t)(wr * 64 + (lane & 15)) * 80 + (lane >> 4) * 16;
    const uint32_t bOff = (uint32_t)(wc * 32 + (lane & 7) + ((lane >> 4) & 1) * 8) * 80 +
                          ((lane >> 3) & 1) * 16;

    for (int cc = 0; cc < 48; ++cc) {
        if (cc < 47) {
            P1_STAGE(cc + 1, (cc + 1) & 1);
            asm volatile("cp.async.wait_group 1;" ::: "memory");
        } else {
            asm volatile("cp.async.wait_group 0;" ::: "memory");
        }
        __syncthreads();
        uint32_t sA = sb + (cc & 1) * 10240, sB = sb + 20480 + (cc & 1) * 10240;
#pragma unroll
        for (int kq = 0; kq < 2; ++kq) {
            uint32_t a[4][4];
#pragma unroll
            for (int mi = 0; mi < 4; ++mi)
                ldsm4(a[mi], sA + aOff + mi * 1280 + kq * 32);
#pragma unroll
            for (int nj = 0; nj < 2; ++nj) {
                uint32_t b[4];
                ldsm4(b, sB + bOff + nj * 1280 + kq * 32);
#pragma unroll
                for (int mi = 0; mi < 4; ++mi) {
                    mma16816(acc[mi][nj * 2], a[mi], b);
                    mma16816(acc[mi][nj * 2 + 1], a[mi], b + 2);
                }
            }
        }
        __syncthreads();
    }

    // epilogue: bias add, exp, split-store P, row sums
#pragma unroll
    for (int mi = 0; mi < 4; ++mi) {
#pragma unroll
        for (int h = 0; h < 2; ++h) {
            int rloc = wr * 64 + mi * 16 + (lane >> 2) + h * 8;
            size_t rb = (size_t)(m0 + rloc) * NN;
            float rs = 0.0f;
#pragma unroll
            for (int ni = 0; ni < 4; ++ni) {
                int col = n0 + wc * 32 + ni * 8 + (lane & 3) * 2;
                float2 s2 = *(const float2*)(sp + rb + col);
                float2 e2 = *(const float2*)(ed + rb + col);
                float p0 = __expf(acc[mi][ni][h * 2] * SCALE + s2.x + e2.x);
                float p1 = __expf(acc[mi][ni][h * 2 + 1] * SCALE + s2.y + e2.y);
                __nv_bfloat16 h0 = __float2bfloat16(p0), h1 = __float2bfloat16(p1);
                *(uint32_t*)(gP_hi + rb + col) = pack2(h0, h1);
                *(uint32_t*)(gP_lo + rb + col) =
                    pack2(__float2bfloat16(p0 - __bfloat162float(h0)),
                          __float2bfloat16(p1 - __bfloat162float(h1)));
                rs += p0 + p1;
            }
            rs += __shfl_xor_sync(0xffffffffu, rs, 1);
            rs += __shfl_xor_sync(0xffffffffu, rs, 2);
            if ((lane & 3) == 0) smem_l[rloc * 4 + wc] = rs;
        }
    }
    __syncthreads();
    if (t < 128) {
        float s = smem_l[t * 4] + smem_l[t * 4 + 1] + smem_l[t * 4 + 2] + smem_l[t * 4 + 3];
        g_lpart[(size_t)blockIdx.x * NN + m0 + t] = s;
    }
}

// ---------------------------------------------------------------------------
// l reduce (deterministic)
// ---------------------------------------------------------------------------
__global__ void lreduce_kernel() {
    int r = blockIdx.x * 256 + threadIdx.x;
    float s = 0.0f;
    for (int b = 0; b < 64; ++b) s += g_lpart[(size_t)b * NN + r];
    g_l[r] = s;
}

// ---------------------------------------------------------------------------
// Pass 2: O = (Ph*Vh + Ph*Vl + Pl*Vh) / l. CTA 64x256, warps 2x4 (warp 32x64).
// 2 CTAs/SM (smem 50KB). 768 chunks = 3 terms x 256 (K=8192/32).
// ---------------------------------------------------------------------------
__global__ __launch_bounds__(256, 2)
void pass2_kernel(float* __restrict__ outp) {
    extern __shared__ char smem[];
    const int t = threadIdx.x, wid = t >> 5, lane = t & 31;
    const int n0 = blockIdx.x * 256, m0 = blockIdx.y * 64;
    const uint32_t sb = smem_u32(smem);
    const int wr = wid >> 2, wc = wid & 3;

    float acc[2][8][4];
#pragma unroll
    for (int mi = 0; mi < 2; ++mi)
#pragma unroll
        for (int ni = 0; ni < 8; ++ni)
#pragma unroll
            for (int q = 0; q < 4; ++q) acc[mi][ni][q] = 0.0f;

    const int sr = t >> 2, sc = t & 3;

#define P2_STAGE(cc, buf)                                                            \
    {                                                                                \
        int term_ = (cc) >> 8, kk_ = ((cc) & 255) * 32;                              \
        const __nv_bfloat16* Aa_ = (term_ == 2) ? gP_lo : gP_hi;                     \
        const __nv_bfloat16* Bb_ = (term_ == 1) ? gvt_lo : gvt_hi;                   \
        uint32_t da_ = sb + (buf) * 5120, db_ = sb + 10240 + (buf) * 20480;          \
        const __nv_bfloat16* As_ = Aa_ + (size_t)m0 * NN + kk_;                      \
        const __nv_bfloat16* Bs_ = Bb_ + (size_t)n0 * NN + kk_;                      \
        cpa16(da_ + sr * 80 + sc * 16, As_ + (size_t)sr * NN + sc * 8);              \
        _Pragma("unroll")                                                            \
        for (int i_ = 0; i_ < 4; ++i_) {                                             \
            int r_ = sr + i_ * 64;                                                   \
            cpa16(db_ + r_ * 80 + sc * 16, Bs_ + (size_t)r_ * NN + sc * 8);          \
        }                                                                            \
        cpa_commit();                                                                \
    }

    P2_STAGE(0, 0);
    const uint32_t aOff = (uint32_t)(wr * 32 + (lane & 15)) * 80 + (lane >> 4) * 16;
    const uint32_t bOff = (uint32_t)(wc * 64 + (lane & 7) + ((lane >> 4) & 1) * 8) * 80 +
                          ((lane >> 3) & 1) * 16;

    for (int cc = 0; cc < 768; ++cc) {
        if (cc < 767) {
            P2_STAGE(cc + 1, (cc + 1) & 1);
            asm volatile("cp.async.wait_group 1;" ::: "memory");
        } else {
            asm volatile("cp.async.wait_group 0;" ::: "memory");
        }
        __syncthreads();
        uint32_t sA = sb + (cc & 1) * 5120, sB = sb + 10240 + (cc & 1) * 20480;
#pragma unroll
        for (int kq = 0; kq < 2; ++kq) {
            uint32_t a0[4], a1[4];
            ldsm4(a0, sA + aOff + kq * 32);
            ldsm4(a1, sA + aOff + 1280 + kq * 32);
#pragma unroll
            for (int nj = 0; nj < 4; ++nj) {
                uint32_t b[4];
                ldsm4(b, sB + bOff + nj * 1280 + kq * 32);
                mma16816(acc[0][nj * 2], a0, b);
                mma16816(acc[0][nj * 2 + 1], a0, b + 2);
                mma16816(acc[1][nj * 2], a1, b);
                mma16816(acc[1][nj * 2 + 1], a1, b + 2);
            }
        }
        __syncthreads();
    }

    // epilogue: divide by l, store
#pragma unroll
    for (int mi = 0; mi < 2; ++mi) {
#pragma unroll
        for (int h = 0; h < 2; ++h) {
            int row = m0 + wr * 32 + mi * 16 + (lane >> 2) + h * 8;
            float inv = 1.0f / g_l[row];
#pragma unroll
            for (int ni = 0; ni < 8; ++ni) {
                int col = n0 + wc * 64 + ni * 8 + (lane & 3) * 2;
                float2 o;
                o.x = acc[mi][ni][h * 2] * inv;
                o.y = acc[mi][ni][h * 2 + 1] * inv;
                *(float2*)(outp + (size_t)row * DD + col) = o;
            }
        }
    }
}

// ---------------------------------------------------------------------------
extern "C" void kernel_launch(void* const* d_in, const int* in_sizes, int n_in,
                              void* d_out, int out_size) {
    const float* x       = (const float*)d_in[0];
    const float* spatial = (const float*)d_in[1];
    const float* edge    = (const float*)d_in[2];
    const float* Wq      = (const float*)d_in[3];
    const float* bq      = (const float*)d_in[4];
    const float* Wk      = (const float*)d_in[5];
    const float* bk      = (const float*)d_in[6];
    const float* Wv      = (const float*)d_in[7];
    const float* bv      = (const float*)d_in[8];
    float* out           = (float*)d_out;

    cudaFuncSetAttribute(pass2_kernel, cudaFuncAttributeMaxDynamicSharedMemorySize, 51200);

    split_kernel<<<4864, 256>>>(x, Wq, Wk, Wv);
    proj_kernel<<<dim3(4, 64, 3), 256>>>(bq, bk, bv);
    vtrans_kernel<<<dim3(NN / 32, DD / 32), 256>>>();
    pass1_kernel<<<dim3(64, 64), 256>>>(spatial, edge);
    lreduce_kernel<<<32, 256>>>();
    pass2_kernel<<<dim3(2, 128), 256, 51200>>>(out);
}

// round 6
// speedup vs baseline: 7.8022x; 1.3266x over previous
#include <cuda_runtime.h>
#include <cuda_bf16.h>
#include <stdint.h>
#include <math.h>

#define NN 8192
#define DD 512
#define SCALE 0.044194173824159216f

// ----------------- device scratch (allocation-free rule) -----------------
__device__ float g_v[NN * DD];
__device__ __nv_bfloat16 gx_hi[NN * DD], gx_lo[NN * DD];
__device__ __nv_bfloat16 gw_hi[3 * DD * DD], gw_lo[3 * DD * DD];
__device__ __nv_bfloat16 gq_hi[NN * DD], gq_lo[NN * DD];
__device__ __nv_bfloat16 gk_hi[NN * DD], gk_lo[NN * DD];
__device__ __nv_bfloat16 gvt_hi[DD * NN], gvt_lo[DD * NN];
__device__ __nv_bfloat16 gP_hi[(size_t)NN * NN], gP_lo[(size_t)NN * NN];
__device__ float g_lpart[64 * NN];
__device__ float g_l[NN];

// ----------------- helpers -----------------
__device__ __forceinline__ uint32_t smem_u32(const void* p) {
    uint32_t a;
    asm("{ .reg .u64 t; cvta.to.shared.u64 t, %1; cvt.u32.u64 %0, t; }" : "=r"(a) : "l"(p));
    return a;
}
__device__ __forceinline__ uint32_t pack2(__nv_bfloat16 a, __nv_bfloat16 b) {
    return (uint32_t)__bfloat16_as_ushort(a) | ((uint32_t)__bfloat16_as_ushort(b) << 16);
}
__device__ __forceinline__ void cpa16(uint32_t dst, const void* src) {
    asm volatile("cp.async.cg.shared.global [%0], [%1], 16;" :: "r"(dst), "l"(src));
}
__device__ __forceinline__ void cpa_commit() {
    asm volatile("cp.async.commit_group;" ::: "memory");
}
__device__ __forceinline__ void ldsm4(uint32_t* r, uint32_t addr) {
    asm volatile("ldmatrix.sync.aligned.m8n8.x4.shared.b16 {%0,%1,%2,%3}, [%4];"
                 : "=r"(r[0]), "=r"(r[1]), "=r"(r[2]), "=r"(r[3]) : "r"(addr));
}
__device__ __forceinline__ void mma16816(float* c, const uint32_t* a, const uint32_t* b) {
    asm volatile(
        "mma.sync.aligned.m16n8k16.row.col.f32.bf16.bf16.f32 "
        "{%0,%1,%2,%3}, {%4,%5,%6,%7}, {%8,%9}, {%0,%1,%2,%3};"
        : "+f"(c[0]), "+f"(c[1]), "+f"(c[2]), "+f"(c[3])
        : "r"(a[0]), "r"(a[1]), "r"(a[2]), "r"(a[3]), "r"(b[0]), "r"(b[1]));
}

// ---------------------------------------------------------------------------
// Split x and Wq/Wk/Wv into bf16 hi/lo
// ---------------------------------------------------------------------------
__global__ __launch_bounds__(256)
void split_kernel(const float* __restrict__ x, const float* __restrict__ Wq,
                  const float* __restrict__ Wk, const float* __restrict__ Wv) {
    int i4 = blockIdx.x * 256 + threadIdx.x;
    const float4* src;
    uint2 *oh, *ol;
    int off;
    if (i4 < NN * DD / 4) {
        src = (const float4*)x; oh = (uint2*)gx_hi; ol = (uint2*)gx_lo; off = i4;
    } else {
        int r = i4 - NN * DD / 4;
        int wi = r >> 16, rr = r & 65535;
        const float* w = (wi == 0) ? Wq : (wi == 1) ? Wk : Wv;
        src = (const float4*)w; off = rr;
        oh = (uint2*)(gw_hi + (size_t)wi * DD * DD);
        ol = (uint2*)(gw_lo + (size_t)wi * DD * DD);
    }
    float4 v = src[off];
    __nv_bfloat16 h0 = __float2bfloat16(v.x), h1 = __float2bfloat16(v.y);
    __nv_bfloat16 h2 = __float2bfloat16(v.z), h3 = __float2bfloat16(v.w);
    uint2 H, L;
    H.x = pack2(h0, h1);
    H.y = pack2(h2, h3);
    L.x = pack2(__float2bfloat16(v.x - __bfloat162float(h0)),
                __float2bfloat16(v.y - __bfloat162float(h1)));
    L.y = pack2(__float2bfloat16(v.z - __bfloat162float(h2)),
                __float2bfloat16(v.w - __bfloat162float(h3)));
    oh[off] = H;
    ol[off] = L;
}

// ---------------------------------------------------------------------------
// Fused-term GEMM body shared by proj and pass1 (CTA 128x128, warps 2x4).
// Stage layout per buffer (40960B): Ah@0, Al@10240, Bh@20480, Bl@30720.
// ---------------------------------------------------------------------------
#define FUSED_STAGE(AH, AL, BH, BL, cc, buf, LDA)                                 \
    {                                                                             \
        int kk_ = (cc) * 32;                                                      \
        uint32_t d_ = sb + (buf) * 40960;                                         \
        const __nv_bfloat16* ah_ = (AH) + (size_t)m0 * (LDA) + kk_;               \
        const __nv_bfloat16* al_ = (AL) + (size_t)m0 * (LDA) + kk_;               \
        const __nv_bfloat16* bh_ = (BH) + (size_t)n0 * (LDA) + kk_;               \
        const __nv_bfloat16* bl_ = (BL) + (size_t)n0 * (LDA) + kk_;               \
        _Pragma("unroll")                                                         \
        for (int i_ = 0; i_ < 2; ++i_) {                                          \
            int r_ = sr + i_ * 64;                                                \
            uint32_t ro_ = r_ * 80 + sc * 16;                                     \
            size_t go_ = (size_t)r_ * (LDA) + sc * 8;                             \
            cpa16(d_ + ro_, ah_ + go_);                                           \
            cpa16(d_ + 10240 + ro_, al_ + go_);                                   \
            cpa16(d_ + 20480 + ro_, bh_ + go_);                                   \
            cpa16(d_ + 30720 + ro_, bl_ + go_);                                   \
        }                                                                         \
        cpa_commit();                                                             \
    }

#define FUSED_COMPUTE(cc)                                                         \
    {                                                                             \
        uint32_t sA = sb + ((cc) & 1) * 40960, sB = sA + 20480;                   \
        _Pragma("unroll")                                                         \
        for (int kq = 0; kq < 2; ++kq) {                                          \
            uint32_t ah[4][4], al[4][4];                                          \
            _Pragma("unroll")                                                     \
            for (int mi = 0; mi < 4; ++mi)                                        \
                ldsm4(ah[mi], sA + aOff + mi * 1280 + kq * 32);                   \
            _Pragma("unroll")                                                     \
            for (int mi = 0; mi < 4; ++mi)                                        \
                ldsm4(al[mi], sA + 10240 + aOff + mi * 1280 + kq * 32);           \
            _Pragma("unroll")                                                     \
            for (int nj = 0; nj < 2; ++nj) {                                      \
                uint32_t bh[4], bl[4];                                            \
                ldsm4(bh, sB + bOff + nj * 1280 + kq * 32);                       \
                ldsm4(bl, sB + 10240 + bOff + nj * 1280 + kq * 32);               \
                _Pragma("unroll")                                                 \
                for (int mi = 0; mi < 4; ++mi) {                                  \
                    mma16816(acc[mi][nj * 2], ah[mi], bh);                        \
                    mma16816(acc[mi][nj * 2 + 1], ah[mi], bh + 2);                \
                    mma16816(acc[mi][nj * 2], ah[mi], bl);                        \
                    mma16816(acc[mi][nj * 2 + 1], ah[mi], bl + 2);                \
                    mma16816(acc[mi][nj * 2], al[mi], bh);                        \
                    mma16816(acc[mi][nj * 2 + 1], al[mi], bh + 2);                \
                }                                                                 \
            }                                                                     \
        }                                                                         \
    }

// ---------------------------------------------------------------------------
// Tensor-core QKV projection, fused 3-term. z=0:Q, z=1:K (bf16 hi/lo), z=2:V fp32.
// ---------------------------------------------------------------------------
__global__ __launch_bounds__(256, 2)
void proj_kernel(const float* __restrict__ bq, const float* __restrict__ bk,
                 const float* __restrict__ bv) {
    extern __shared__ __align__(128) char smem[];
    const int t = threadIdx.x, wid = t >> 5, lane = t & 31;
    const int z = blockIdx.z;
    const int m0 = blockIdx.y * 128, n0 = blockIdx.x * 128;
    const uint32_t sb = smem_u32(smem);
    const int wr = wid >> 2, wc = wid & 3;
    const __nv_bfloat16* WHz = gw_hi + (size_t)z * DD * DD;
    const __nv_bfloat16* WLz = gw_lo + (size_t)z * DD * DD;

    float acc[4][4][4];
#pragma unroll
    for (int mi = 0; mi < 4; ++mi)
#pragma unroll
        for (int ni = 0; ni < 4; ++ni)
#pragma unroll
            for (int q = 0; q < 4; ++q) acc[mi][ni][q] = 0.0f;

    const int sr = t >> 2, sc = t & 3;
    const uint32_t aOff = (uint32_t)(wr * 64 + (lane & 15)) * 80 + (lane >> 4) * 16;
    const uint32_t bOff = (uint32_t)(wc * 32 + (lane & 7) + ((lane >> 4) & 1) * 8) * 80 +
                          ((lane >> 3) & 1) * 16;

    FUSED_STAGE(gx_hi, gx_lo, WHz, WLz, 0, 0, DD);
    for (int cc = 0; cc < 16; ++cc) {
        asm volatile("cp.async.wait_group 0;" ::: "memory");
        __syncthreads();
        if (cc < 15) FUSED_STAGE(gx_hi, gx_lo, WHz, WLz, cc + 1, (cc + 1) & 1, DD);
        FUSED_COMPUTE(cc);
    }

    const float* bias = (z == 0) ? bq : (z == 1) ? bk : bv;
#pragma unroll
    for (int mi = 0; mi < 4; ++mi) {
#pragma unroll
        for (int h = 0; h < 2; ++h) {
            int row = m0 + wr * 64 + mi * 16 + (lane >> 2) + h * 8;
#pragma unroll
            for (int ni = 0; ni < 4; ++ni) {
                int col = n0 + wc * 32 + ni * 8 + (lane & 3) * 2;
                float2 bb = *(const float2*)(bias + col);
                float v0 = acc[mi][ni][h * 2] + bb.x;
                float v1 = acc[mi][ni][h * 2 + 1] + bb.y;
                if (z == 2) {
                    *(float2*)(g_v + (size_t)row * DD + col) = make_float2(v0, v1);
                } else {
                    __nv_bfloat16* oh = z ? gk_hi : gq_hi;
                    __nv_bfloat16* ol = z ? gk_lo : gq_lo;
                    __nv_bfloat16 h0 = __float2bfloat16(v0), h1 = __float2bfloat16(v1);
                    *(uint32_t*)(oh + (size_t)row * DD + col) = pack2(h0, h1);
                    *(uint32_t*)(ol + (size_t)row * DD + col) =
                        pack2(__float2bfloat16(v0 - __bfloat162float(h0)),
                              __float2bfloat16(v1 - __bfloat162float(h1)));
                }
            }
        }
    }
}

// ---------------------------------------------------------------------------
// V transpose + bf16 split
// ---------------------------------------------------------------------------
__global__ __launch_bounds__(256, 4)
void vtrans_kernel() {
    __shared__ float ts[32][33];
    int j0 = blockIdx.x * 32, d0 = blockIdx.y * 32;
    int tx = threadIdx.x & 31, ty = threadIdx.x >> 5;
#pragma unroll
    for (int i = 0; i < 4; ++i)
        ts[ty + 8 * i][tx] = g_v[(size_t)(j0 + ty + 8 * i) * DD + d0 + tx];
    __syncthreads();
#pragma unroll
    for (int i = 0; i < 4; ++i) {
        float v = ts[tx][ty + 8 * i];
        __nv_bfloat16 h = __float2bfloat16(v);
        __nv_bfloat16 l = __float2bfloat16(v - __bfloat162float(h));
        size_t o = (size_t)(d0 + ty + 8 * i) * NN + j0 + tx;
        gvt_hi[o] = h;
        gvt_lo[o] = l;
    }
}

// ---------------------------------------------------------------------------
// Pass 1: P = exp(scale*Q@K^T + sp + ed), fused 3-term mainloop.
// ---------------------------------------------------------------------------
__global__ __launch_bounds__(256, 2)
void pass1_kernel(const float* __restrict__ sp, const float* __restrict__ ed) {
    extern __shared__ __align__(128) char smem[];
    float* smem_l = (float*)(smem + 81920);
    const int t = threadIdx.x, wid = t >> 5, lane = t & 31;
    const int m0 = blockIdx.y * 128, n0 = blockIdx.x * 128;
    const uint32_t sb = smem_u32(smem);
    const int wr = wid >> 2, wc = wid & 3;

    float acc[4][4][4];
#pragma unroll
    for (int mi = 0; mi < 4; ++mi)
#pragma unroll
        for (int ni = 0; ni < 4; ++ni)
#pragma unroll
            for (int q = 0; q < 4; ++q) acc[mi][ni][q] = 0.0f;

    const int sr = t >> 2, sc = t & 3;
    const uint32_t aOff = (uint32_t)(wr * 64 + (lane & 15)) * 80 + (lane >> 4) * 16;
    const uint32_t bOff = (uint32_t)(wc * 32 + (lane & 7) + ((lane >> 4) & 1) * 8) * 80 +
                          ((lane >> 3) & 1) * 16;

    FUSED_STAGE(gq_hi, gq_lo, gk_hi, gk_lo, 0, 0, DD);
    for (int cc = 0; cc < 16; ++cc) {
        asm volatile("cp.async.wait_group 0;" ::: "memory");
        __syncthreads();
        if (cc < 15) FUSED_STAGE(gq_hi, gq_lo, gk_hi, gk_lo, cc + 1, (cc + 1) & 1, DD);
        FUSED_COMPUTE(cc);
    }

    // epilogue: bias add, exp, split-store P, row sums
#pragma unroll
    for (int mi = 0; mi < 4; ++mi) {
#pragma unroll
        for (int h = 0; h < 2; ++h) {
            int rloc = wr * 64 + mi * 16 + (lane >> 2) + h * 8;
            size_t rb = (size_t)(m0 + rloc) * NN;
            float rs = 0.0f;
#pragma unroll
            for (int ni = 0; ni < 4; ++ni) {
                int col = n0 + wc * 32 + ni * 8 + (lane & 3) * 2;
                float2 s2 = *(const float2*)(sp + rb + col);
                float2 e2 = *(const float2*)(ed + rb + col);
                float p0 = __expf(acc[mi][ni][h * 2] * SCALE + s2.x + e2.x);
                float p1 = __expf(acc[mi][ni][h * 2 + 1] * SCALE + s2.y + e2.y);
                __nv_bfloat16 h0 = __float2bfloat16(p0), h1 = __float2bfloat16(p1);
                *(uint32_t*)(gP_hi + rb + col) = pack2(h0, h1);
                *(uint32_t*)(gP_lo + rb + col) =
                    pack2(__float2bfloat16(p0 - __bfloat162float(h0)),
                          __float2bfloat16(p1 - __bfloat162float(h1)));
                rs += p0 + p1;
            }
            rs += __shfl_xor_sync(0xffffffffu, rs, 1);
            rs += __shfl_xor_sync(0xffffffffu, rs, 2);
            if ((lane & 3) == 0) smem_l[rloc * 4 + wc] = rs;
        }
    }
    __syncthreads();
    if (t < 128) {
        float s = smem_l[t * 4] + smem_l[t * 4 + 1] + smem_l[t * 4 + 2] + smem_l[t * 4 + 3];
        g_lpart[(size_t)blockIdx.x * NN + m0 + t] = s;
    }
}

// ---------------------------------------------------------------------------
// l reduce (deterministic)
// ---------------------------------------------------------------------------
__global__ void lreduce_kernel() {
    int r = blockIdx.x * 256 + threadIdx.x;
    float s = 0.0f;
    for (int b = 0; b < 64; ++b) s += g_lpart[(size_t)b * NN + r];
    g_l[r] = s;
}

// ---------------------------------------------------------------------------
// Pass 2: O = (Ph*Vh + Ph*Vl + Pl*Vh) / l, fused 3-term.
// CTA 64x256, warps 2x4 (warp 32x64). Stage: Ph@0(5120) Pl@5120 Vh@10240(20480)
// Vl@30720; buffer stride 51200.
// ---------------------------------------------------------------------------
__global__ __launch_bounds__(256, 2)
void pass2_kernel(float* __restrict__ outp) {
    extern __shared__ __align__(128) char smem[];
    const int t = threadIdx.x, wid = t >> 5, lane = t & 31;
    const int n0 = blockIdx.x * 256, m0 = blockIdx.y * 64;
    const uint32_t sb = smem_u32(smem);
    const int wr = wid >> 2, wc = wid & 3;

    float acc[2][8][4];
#pragma unroll
    for (int mi = 0; mi < 2; ++mi)
#pragma unroll
        for (int ni = 0; ni < 8; ++ni)
#pragma unroll
            for (int q = 0; q < 4; ++q) acc[mi][ni][q] = 0.0f;

    const int sr = t >> 2, sc = t & 3;

#define P2_STAGE(cc, buf)                                                          \
    {                                                                              \
        int kk_ = (cc) * 32;                                                       \
        uint32_t d_ = sb + (buf) * 51200;                                          \
        const __nv_bfloat16* ph_ = gP_hi + (size_t)m0 * NN + kk_;                  \
        const __nv_bfloat16* pl_ = gP_lo + (size_t)m0 * NN + kk_;                  \
        const __nv_bfloat16* vh_ = gvt_hi + (size_t)n0 * NN + kk_;                 \
        const __nv_bfloat16* vl_ = gvt_lo + (size_t)n0 * NN + kk_;                 \
        {                                                                          \
            uint32_t ro_ = sr * 80 + sc * 16;                                      \
            size_t go_ = (size_t)sr * NN + sc * 8;                                 \
            cpa16(d_ + ro_, ph_ + go_);                                            \
            cpa16(d_ + 5120 + ro_, pl_ + go_);                                     \
        }                                                                          \
        _Pragma("unroll")                                                          \
        for (int i_ = 0; i_ < 4; ++i_) {                                           \
            int r_ = sr + i_ * 64;                                                 \
            uint32_t ro_ = r_ * 80 + sc * 16;                                      \
            size_t go_ = (size_t)r_ * NN + sc * 8;                                 \
            cpa16(d_ + 10240 + ro_, vh_ + go_);                                    \
            cpa16(d_ + 30720 + ro_, vl_ + go_);                                    \
        }                                                                          \
        cpa_commit();                                                              \
    }

    const uint32_t aOff = (uint32_t)(wr * 32 + (lane & 15)) * 80 + (lane >> 4) * 16;
    const uint32_t bOff = (uint32_t)(wc * 64 + (lane & 7) + ((lane >> 4) & 1) * 8) * 80 +
                          ((lane >> 3) & 1) * 16;

    P2_STAGE(0, 0);
    for (int cc = 0; cc < 256; ++cc) {
        asm volatile("cp.async.wait_group 0;" ::: "memory");
        __syncthreads();
        if (cc < 255) P2_STAGE(cc + 1, (cc + 1) & 1);
        uint32_t sA = sb + (cc & 1) * 51200, sB = sA + 10240;
#pragma unroll
        for (int kq = 0; kq < 2; ++kq) {
            uint32_t ah[2][4], al[2][4];
#pragma unroll
            for (int mi = 0; mi < 2; ++mi)
                ldsm4(ah[mi], sA + aOff + mi * 1280 + kq * 32);
#pragma unroll
            for (int mi = 0; mi < 2; ++mi)
                ldsm4(al[mi], sA + 5120 + aOff + mi * 1280 + kq * 32);
#pragma unroll
            for (int nj = 0; nj < 4; ++nj) {
                uint32_t bh[4], bl[4];
                ldsm4(bh, sB + bOff + nj * 1280 + kq * 32);
                ldsm4(bl, sB + 20480 + bOff + nj * 1280 + kq * 32);
#pragma unroll
                for (int mi = 0; mi < 2; ++mi) {
                    mma16816(acc[mi][nj * 2], ah[mi], bh);
                    mma16816(acc[mi][nj * 2 + 1], ah[mi], bh + 2);
                    mma16816(acc[mi][nj * 2], ah[mi], bl);
                    mma16816(acc[mi][nj * 2 + 1], ah[mi], bl + 2);
                    mma16816(acc[mi][nj * 2], al[mi], bh);
                    mma16816(acc[mi][nj * 2 + 1], al[mi], bh + 2);
                }
            }
        }
    }

    // epilogue: divide by l, store
#pragma unroll
    for (int mi = 0; mi < 2; ++mi) {
#pragma unroll
        for (int h = 0; h < 2; ++h) {
            int row = m0 + wr * 32 + mi * 16 + (lane >> 2) + h * 8;
            float inv = 1.0f / g_l[row];
#pragma unroll
            for (int ni = 0; ni < 8; ++ni) {
                int col = n0 + wc * 64 + ni * 8 + (lane & 3) * 2;
                float2 o;
                o.x = acc[mi][ni][h * 2] * inv;
                o.y = acc[mi][ni][h * 2 + 1] * inv;
                *(float2*)(outp + (size_t)row * DD + col) = o;
            }
        }
    }
}

// ---------------------------------------------------------------------------
extern "C" void kernel_launch(void* const* d_in, const int* in_sizes, int n_in,
                              void* d_out, int out_size) {
    const float* x       = (const float*)d_in[0];
    const float* spatial = (const float*)d_in[1];
    const float* edge    = (const float*)d_in[2];
    const float* Wq      = (const float*)d_in[3];
    const float* bq      = (const float*)d_in[4];
    const float* Wk      = (const float*)d_in[5];
    const float* bk      = (const float*)d_in[6];
    const float* Wv      = (const float*)d_in[7];
    const float* bv      = (const float*)d_in[8];
    float* out           = (float*)d_out;

    cudaFuncSetAttribute(proj_kernel, cudaFuncAttributeMaxDynamicSharedMemorySize, 81920);
    cudaFuncSetAttribute(pass1_kernel, cudaFuncAttributeMaxDynamicSharedMemorySize, 84480);
    cudaFuncSetAttribute(pass2_kernel, cudaFuncAttributeMaxDynamicSharedMemorySize, 102400);

    split_kernel<<<4864, 256>>>(x, Wq, Wk, Wv);
    proj_kernel<<<dim3(4, 64, 3), 256, 81920>>>(bq, bk, bv);
    vtrans_kernel<<<dim3(NN / 32, DD / 32), 256>>>();
    pass1_kernel<<<dim3(64, 64), 256, 84480>>>(spatial, edge);
    lreduce_kernel<<<32, 256>>>();
    pass2_kernel<<<dim3(2, 128), 256, 102400>>>(out);
}

// round 7
// speedup vs baseline: 8.1600x; 1.0459x over previous
#include <cuda_runtime.h>
#include <cuda_bf16.h>
#include <stdint.h>
#include <math.h>

#define NN 8192
#define DD 512
#define SCALE 0.044194173824159216f

// ----------------- device scratch (allocation-free rule) -----------------
__device__ float g_v[NN * DD];
__device__ __nv_bfloat16 gx_hi[NN * DD], gx_lo[NN * DD];
__device__ __nv_bfloat16 gw_hi[3 * DD * DD], gw_lo[3 * DD * DD];
__device__ __nv_bfloat16 gq_hi[NN * DD], gq_lo[NN * DD];
__device__ __nv_bfloat16 gk_hi[NN * DD], gk_lo[NN * DD];
__device__ __nv_bfloat16 gvt_hi[DD * NN], gvt_lo[DD * NN];
__device__ __nv_bfloat16 gP_hi[(size_t)NN * NN], gP_lo[(size_t)NN * NN];
__device__ float g_lpart[64 * NN];
__device__ float g_l[NN];

// ----------------- helpers -----------------
__device__ __forceinline__ uint32_t smem_u32(const void* p) {
    uint32_t a;
    asm("{ .reg .u64 t; cvta.to.shared.u64 t, %1; cvt.u32.u64 %0, t; }" : "=r"(a) : "l"(p));
    return a;
}
__device__ __forceinline__ uint32_t pack2(__nv_bfloat16 a, __nv_bfloat16 b) {
    return (uint32_t)__bfloat16_as_ushort(a) | ((uint32_t)__bfloat16_as_ushort(b) << 16);
}
__device__ __forceinline__ void cpa16(uint32_t dst, const void* src) {
    asm volatile("cp.async.cg.shared.global [%0], [%1], 16;" :: "r"(dst), "l"(src));
}
__device__ __forceinline__ void cpa_commit() {
    asm volatile("cp.async.commit_group;" ::: "memory");
}
__device__ __forceinline__ void ldsm4(uint32_t* r, uint32_t addr) {
    asm volatile("ldmatrix.sync.aligned.m8n8.x4.shared.b16 {%0,%1,%2,%3}, [%4];"
                 : "=r"(r[0]), "=r"(r[1]), "=r"(r[2]), "=r"(r[3]) : "r"(addr));
}
__device__ __forceinline__ void mma16816(float* c, const uint32_t* a, const uint32_t* b) {
    asm volatile(
        "mma.sync.aligned.m16n8k16.row.col.f32.bf16.bf16.f32 "
        "{%0,%1,%2,%3}, {%4,%5,%6,%7}, {%8,%9}, {%0,%1,%2,%3};"
        : "+f"(c[0]), "+f"(c[1]), "+f"(c[2]), "+f"(c[3])
        : "r"(a[0]), "r"(a[1]), "r"(a[2]), "r"(a[3]), "r"(b[0]), "r"(b[1]));
}

// ---------------------------------------------------------------------------
// Split x and Wq/Wk/Wv into bf16 hi/lo
// ---------------------------------------------------------------------------
__global__ __launch_bounds__(256)
void split_kernel(const float* __restrict__ x, const float* __restrict__ Wq,
                  const float* __restrict__ Wk, const float* __restrict__ Wv) {
    int i4 = blockIdx.x * 256 + threadIdx.x;
    const float4* src;
    uint2 *oh, *ol;
    int off;
    if (i4 < NN * DD / 4) {
        src = (const float4*)x; oh = (uint2*)gx_hi; ol = (uint2*)gx_lo; off = i4;
    } else {
        int r = i4 - NN * DD / 4;
        int wi = r >> 16, rr = r & 65535;
        const float* w = (wi == 0) ? Wq : (wi == 1) ? Wk : Wv;
        src = (const float4*)w; off = rr;
        oh = (uint2*)(gw_hi + (size_t)wi * DD * DD);
        ol = (uint2*)(gw_lo + (size_t)wi * DD * DD);
    }
    float4 v = src[off];
    __nv_bfloat16 h0 = __float2bfloat16(v.x), h1 = __float2bfloat16(v.y);
    __nv_bfloat16 h2 = __float2bfloat16(v.z), h3 = __float2bfloat16(v.w);
    uint2 H, L;
    H.x = pack2(h0, h1);
    H.y = pack2(h2, h3);
    L.x = pack2(__float2bfloat16(v.x - __bfloat162float(h0)),
                __float2bfloat16(v.y - __bfloat162float(h1)));
    L.y = pack2(__float2bfloat16(v.z - __bfloat162float(h2)),
                __float2bfloat16(v.w - __bfloat162float(h3)));
    oh[off] = H;
    ol[off] = L;
}

// ---------------------------------------------------------------------------
// Fused-term GEMM body (CTA 128x128, warps 2x4, warp 64x32).
// Stage layout per buffer (40960B): Ah@0, Al@10240, Bh@20480, Bl@30720.
// ---------------------------------------------------------------------------
#define FUSED_STAGE(AH, AL, BH, BL, cc, buf, LDA)                                 \
    {                                                                             \
        int kk_ = (cc) * 32;                                                      \
        uint32_t d_ = sb + (buf) * 40960;                                         \
        const __nv_bfloat16* ah_ = (AH) + (size_t)m0 * (LDA) + kk_;               \
        const __nv_bfloat16* al_ = (AL) + (size_t)m0 * (LDA) + kk_;               \
        const __nv_bfloat16* bh_ = (BH) + (size_t)n0 * (LDA) + kk_;               \
        const __nv_bfloat16* bl_ = (BL) + (size_t)n0 * (LDA) + kk_;               \
        _Pragma("unroll")                                                         \
        for (int i_ = 0; i_ < 2; ++i_) {                                          \
            int r_ = sr + i_ * 64;                                                \
            uint32_t ro_ = r_ * 80 + sc * 16;                                     \
            size_t go_ = (size_t)r_ * (LDA) + sc * 8;                             \
            cpa16(d_ + ro_, ah_ + go_);                                           \
            cpa16(d_ + 10240 + ro_, al_ + go_);                                   \
            cpa16(d_ + 20480 + ro_, bh_ + go_);                                   \
            cpa16(d_ + 30720 + ro_, bl_ + go_);                                   \
        }                                                                         \
        cpa_commit();                                                             \
    }

#define FUSED_COMPUTE(cc)                                                         \
    {                                                                             \
        uint32_t sA = sb + ((cc) & 1) * 40960, sB = sA + 20480;                   \
        _Pragma("unroll")                                                         \
        for (int kq = 0; kq < 2; ++kq) {                                          \
            uint32_t ah[4][4], al[4][4];                                          \
            _Pragma("unroll")                                                     \
            for (int mi = 0; mi < 4; ++mi)                                        \
                ldsm4(ah[mi], sA + aOff + mi * 1280 + kq * 32);                   \
            _Pragma("unroll")                                                     \
            for (int mi = 0; mi < 4; ++mi)                                        \
                ldsm4(al[mi], sA + 10240 + aOff + mi * 1280 + kq * 32);           \
            _Pragma("unroll")                                                     \
            for (int nj = 0; nj < 2; ++nj) {                                      \
                uint32_t bh[4], bl[4];                                            \
                ldsm4(bh, sB + bOff + nj * 1280 + kq * 32);                       \
                ldsm4(bl, sB + 10240 + bOff + nj * 1280 + kq * 32);               \
                _Pragma("unroll")                                                 \
                for (int mi = 0; mi < 4; ++mi) {                                  \
                    mma16816(acc[mi][nj * 2], ah[mi], bh);                        \
                    mma16816(acc[mi][nj * 2 + 1], ah[mi], bh + 2);                \
                    mma16816(acc[mi][nj * 2], ah[mi], bl);                        \
                    mma16816(acc[mi][nj * 2 + 1], ah[mi], bl + 2);                \
                    mma16816(acc[mi][nj * 2], al[mi], bh);                        \
                    mma16816(acc[mi][nj * 2 + 1], al[mi], bh + 2);                \
                }                                                                 \
            }                                                                     \
        }                                                                         \
    }

// ---------------------------------------------------------------------------
// Tensor-core QKV projection, fused 3-term. z=0:Q, z=1:K (bf16 hi/lo), z=2:V fp32.
// ---------------------------------------------------------------------------
__global__ __launch_bounds__(256, 2)
void proj_kernel(const float* __restrict__ bq, const float* __restrict__ bk,
                 const float* __restrict__ bv) {
    extern __shared__ __align__(128) char smem[];
    const int t = threadIdx.x, wid = t >> 5, lane = t & 31;
    const int z = blockIdx.z;
    const int m0 = blockIdx.y * 128, n0 = blockIdx.x * 128;
    const uint32_t sb = smem_u32(smem);
    const int wr = wid >> 2, wc = wid & 3;
    const __nv_bfloat16* WHz = gw_hi + (size_t)z * DD * DD;
    const __nv_bfloat16* WLz = gw_lo + (size_t)z * DD * DD;

    float acc[4][4][4];
#pragma unroll
    for (int mi = 0; mi < 4; ++mi)
#pragma unroll
        for (int ni = 0; ni < 4; ++ni)
#pragma unroll
            for (int q = 0; q < 4; ++q) acc[mi][ni][q] = 0.0f;

    const int sr = t >> 2, sc = t & 3;
    const uint32_t aOff = (uint32_t)(wr * 64 + (lane & 15)) * 80 + (lane >> 4) * 16;
    const uint32_t bOff = (uint32_t)(wc * 32 + (lane & 7) + ((lane >> 4) & 1) * 8) * 80 +
                          ((lane >> 3) & 1) * 16;

    FUSED_STAGE(gx_hi, gx_lo, WHz, WLz, 0, 0, DD);
    for (int cc = 0; cc < 16; ++cc) {
        asm volatile("cp.async.wait_group 0;" ::: "memory");
        __syncthreads();
        if (cc < 15) FUSED_STAGE(gx_hi, gx_lo, WHz, WLz, cc + 1, (cc + 1) & 1, DD);
        FUSED_COMPUTE(cc);
    }

    const float* bias = (z == 0) ? bq : (z == 1) ? bk : bv;
#pragma unroll
    for (int mi = 0; mi < 4; ++mi) {
#pragma unroll
        for (int h = 0; h < 2; ++h) {
            int row = m0 + wr * 64 + mi * 16 + (lane >> 2) + h * 8;
#pragma unroll
            for (int ni = 0; ni < 4; ++ni) {
                int col = n0 + wc * 32 + ni * 8 + (lane & 3) * 2;
                float2 bb = *(const float2*)(bias + col);
                float v0 = acc[mi][ni][h * 2] + bb.x;
                float v1 = acc[mi][ni][h * 2 + 1] + bb.y;
                if (z == 2) {
                    *(float2*)(g_v + (size_t)row * DD + col) = make_float2(v0, v1);
                } else {
                    __nv_bfloat16* oh = z ? gk_hi : gq_hi;
                    __nv_bfloat16* ol = z ? gk_lo : gq_lo;
                    __nv_bfloat16 h0 = __float2bfloat16(v0), h1 = __float2bfloat16(v1);
                    *(uint32_t*)(oh + (size_t)row * DD + col) = pack2(h0, h1);
                    *(uint32_t*)(ol + (size_t)row * DD + col) =
                        pack2(__float2bfloat16(v0 - __bfloat162float(h0)),
                              __float2bfloat16(v1 - __bfloat162float(h1)));
                }
            }
        }
    }
}

// ---------------------------------------------------------------------------
// V transpose + bf16 split
// ---------------------------------------------------------------------------
__global__ __launch_bounds__(256, 4)
void vtrans_kernel() {
    __shared__ float ts[32][33];
    int j0 = blockIdx.x * 32, d0 = blockIdx.y * 32;
    int tx = threadIdx.x & 31, ty = threadIdx.x >> 5;
#pragma unroll
    for (int i = 0; i < 4; ++i)
        ts[ty + 8 * i][tx] = g_v[(size_t)(j0 + ty + 8 * i) * DD + d0 + tx];
    __syncthreads();
#pragma unroll
    for (int i = 0; i < 4; ++i) {
        float v = ts[tx][ty + 8 * i];
        __nv_bfloat16 h = __float2bfloat16(v);
        __nv_bfloat16 l = __float2bfloat16(v - __bfloat162float(h));
        size_t o = (size_t)(d0 + ty + 8 * i) * NN + j0 + tx;
        gvt_hi[o] = h;
        gvt_lo[o] = l;
    }
}

// ---------------------------------------------------------------------------
// Pass 1: P = exp(scale*Q@K^T + sp + ed), fused 3-term mainloop.
// ---------------------------------------------------------------------------
__global__ __launch_bounds__(256, 2)
void pass1_kernel(const float* __restrict__ sp, const float* __restrict__ ed) {
    extern __shared__ __align__(128) char smem[];
    float* smem_l = (float*)(smem + 81920);
    const int t = threadIdx.x, wid = t >> 5, lane = t & 31;
    const int m0 = blockIdx.y * 128, n0 = blockIdx.x * 128;
    const uint32_t sb = smem_u32(smem);
    const int wr = wid >> 2, wc = wid & 3;

    float acc[4][4][4];
#pragma unroll
    for (int mi = 0; mi < 4; ++mi)
#pragma unroll
        for (int ni = 0; ni < 4; ++ni)
#pragma unroll
            for (int q = 0; q < 4; ++q) acc[mi][ni][q] = 0.0f;

    const int sr = t >> 2, sc = t & 3;
    const uint32_t aOff = (uint32_t)(wr * 64 + (lane & 15)) * 80 + (lane >> 4) * 16;
    const uint32_t bOff = (uint32_t)(wc * 32 + (lane & 7) + ((lane >> 4) & 1) * 8) * 80 +
                          ((lane >> 3) & 1) * 16;

    FUSED_STAGE(gq_hi, gq_lo, gk_hi, gk_lo, 0, 0, DD);
    for (int cc = 0; cc < 16; ++cc) {
        asm volatile("cp.async.wait_group 0;" ::: "memory");
        __syncthreads();
        if (cc < 15) FUSED_STAGE(gq_hi, gq_lo, gk_hi, gk_lo, cc + 1, (cc + 1) & 1, DD);
        FUSED_COMPUTE(cc);
    }

    // epilogue: bias add, exp, split-store P, row sums
#pragma unroll
    for (int mi = 0; mi < 4; ++mi) {
#pragma unroll
        for (int h = 0; h < 2; ++h) {
            int rloc = wr * 64 + mi * 16 + (lane >> 2) + h * 8;
            size_t rb = (size_t)(m0 + rloc) * NN;
            float rs = 0.0f;
#pragma unroll
            for (int ni = 0; ni < 4; ++ni) {
                int col = n0 + wc * 32 + ni * 8 + (lane & 3) * 2;
                float2 s2 = *(const float2*)(sp + rb + col);
                float2 e2 = *(const float2*)(ed + rb + col);
                float p0 = __expf(acc[mi][ni][h * 2] * SCALE + s2.x + e2.x);
                float p1 = __expf(acc[mi][ni][h * 2 + 1] * SCALE + s2.y + e2.y);
                __nv_bfloat16 h0 = __float2bfloat16(p0), h1 = __float2bfloat16(p1);
                *(uint32_t*)(gP_hi + rb + col) = pack2(h0, h1);
                *(uint32_t*)(gP_lo + rb + col) =
                    pack2(__float2bfloat16(p0 - __bfloat162float(h0)),
                          __float2bfloat16(p1 - __bfloat162float(h1)));
                rs += p0 + p1;
            }
            rs += __shfl_xor_sync(0xffffffffu, rs, 1);
            rs += __shfl_xor_sync(0xffffffffu, rs, 2);
            if ((lane & 3) == 0) smem_l[rloc * 4 + wc] = rs;
        }
    }
    __syncthreads();
    if (t < 128) {
        float s = smem_l[t * 4] + smem_l[t * 4 + 1] + smem_l[t * 4 + 2] + smem_l[t * 4 + 3];
        g_lpart[(size_t)blockIdx.x * NN + m0 + t] = s;
    }
}

// ---------------------------------------------------------------------------
// l reduce (deterministic)
// ---------------------------------------------------------------------------
__global__ void lreduce_kernel() {
    int r = blockIdx.x * 256 + threadIdx.x;
    float s = 0.0f;
    for (int b = 0; b < 64; ++b) s += g_lpart[(size_t)b * NN + r];
    g_l[r] = s;
}

// ---------------------------------------------------------------------------
// Pass 2: O = (Ph*Vh + Ph*Vl + Pl*Vh) / l, fused 3-term, pass1 topology.
// CTA 128x128 (m x d), warps 2x4 (warp 64x32). A=gP (stride NN), B=gvt (stride NN).
// K = 8192 in 256 chunks of 32.
// ---------------------------------------------------------------------------
__global__ __launch_bounds__(256, 2)
void pass2_kernel(float* __restrict__ outp) {
    extern __shared__ __align__(128) char smem[];
    const int t = threadIdx.x, wid = t >> 5, lane = t & 31;
    const int n0 = blockIdx.x * 128, m0 = blockIdx.y * 128;
    const uint32_t sb = smem_u32(smem);
    const int wr = wid >> 2, wc = wid & 3;

    float acc[4][4][4];
#pragma unroll
    for (int mi = 0; mi < 4; ++mi)
#pragma unroll
        for (int ni = 0; ni < 4; ++ni)
#pragma unroll
            for (int q = 0; q < 4; ++q) acc[mi][ni][q] = 0.0f;

    const int sr = t >> 2, sc = t & 3;
    const uint32_t aOff = (uint32_t)(wr * 64 + (lane & 15)) * 80 + (lane >> 4) * 16;
    const uint32_t bOff = (uint32_t)(wc * 32 + (lane & 7) + ((lane >> 4) & 1) * 8) * 80 +
                          ((lane >> 3) & 1) * 16;

    FUSED_STAGE(gP_hi, gP_lo, gvt_hi, gvt_lo, 0, 0, NN);
    for (int cc = 0; cc < 256; ++cc) {
        asm volatile("cp.async.wait_group 0;" ::: "memory");
        __syncthreads();
        if (cc < 255) FUSED_STAGE(gP_hi, gP_lo, gvt_hi, gvt_lo, cc + 1, (cc + 1) & 1, NN);
        FUSED_COMPUTE(cc);
    }

    // epilogue: divide by l, store
#pragma unroll
    for (int mi = 0; mi < 4; ++mi) {
#pragma unroll
        for (int h = 0; h < 2; ++h) {
            int row = m0 + wr * 64 + mi * 16 + (lane >> 2) + h * 8;
            float inv = 1.0f / g_l[row];
#pragma unroll
            for (int ni = 0; ni < 4; ++ni) {
                int col = n0 + wc * 32 + ni * 8 + (lane & 3) * 2;
                float2 o;
                o.x = acc[mi][ni][h * 2] * inv;
                o.y = acc[mi][ni][h * 2 + 1] * inv;
                *(float2*)(outp + (size_t)row * DD + col) = o;
            }
        }
    }
}

// ---------------------------------------------------------------------------
extern "C" void kernel_launch(void* const* d_in, const int* in_sizes, int n_in,
                              void* d_out, int out_size) {
    const float* x       = (const float*)d_in[0];
    const float* spatial = (const float*)d_in[1];
    const float* edge    = (const float*)d_in[2];
    const float* Wq      = (const float*)d_in[3];
    const float* bq      = (const float*)d_in[4];
    const float* Wk      = (const float*)d_in[5];
    const float* bk      = (const float*)d_in[6];
    const float* Wv      = (const float*)d_in[7];
    const float* bv      = (const float*)d_in[8];
    float* out           = (float*)d_out;

    cudaFuncSetAttribute(proj_kernel, cudaFuncAttributeMaxDynamicSharedMemorySize, 81920);
    cudaFuncSetAttribute(pass1_kernel, cudaFuncAttributeMaxDynamicSharedMemorySize, 84480);
    cudaFuncSetAttribute(pass2_kernel, cudaFuncAttributeMaxDynamicSharedMemorySize, 81920);

    split_kernel<<<4864, 256>>>(x, Wq, Wk, Wv);
    proj_kernel<<<dim3(4, 64, 3), 256, 81920>>>(bq, bk, bv);
    vtrans_kernel<<<dim3(NN / 32, DD / 32), 256>>>();
    pass1_kernel<<<dim3(64, 64), 256, 84480>>>(spatial, edge);
    lreduce_kernel<<<32, 256>>>();
    pass2_kernel<<<dim3(4, 64), 256, 81920>>>(out);
}